// round 5
// baseline (speedup 1.0000x reference)
#include <cuda_runtime.h>
#include <math.h>

// Problem constants: B=256, T=200, X=128, H=512, NU=100, cin=1152.
#define NB 256
#define NT 200
#define NX 128
#define NH 512

// Device-global scratch (allocation-free): x-projections with bias folded.
// Layout [t][b][j], j in [0,100).
__device__ float g_xpu[NT * NB * 100];
__device__ float g_xpr[NT * NB * 100];
__device__ float g_xpn[NT * NB * 100];

// ---------------------------------------------------------------------------
// Prep: g_xp*[t][b][j] = b*1[j] + sum_i x[b][t][i] * W*1[(1024+i)*100 + j]
// grid (200, 16), 256 threads (200 active). Thread: one j, 8 batch rows.
// ---------------------------------------------------------------------------
__global__ __launch_bounds__(256) void prep_xproj_kernel(
    const float* __restrict__ x,
    const float* __restrict__ Wu1, const float* __restrict__ bu1,
    const float* __restrict__ Wr1, const float* __restrict__ br1,
    const float* __restrict__ Wn1, const float* __restrict__ bn1)
{
    int t   = blockIdx.x;          // 0..199
    int bt  = blockIdx.y;          // 0..15
    int tid = threadIdx.x;
    if (tid >= 200) return;
    int j  = tid % 100;
    int s  = tid / 100;            // 0 or 1
    int b0 = bt * 16 + s * 8;

    float au[8], ar[8], an[8];
    float vbu = bu1[j], vbr = br1[j], vbn = bn1[j];
#pragma unroll
    for (int bi = 0; bi < 8; bi++) { au[bi] = vbu; ar[bi] = vbr; an[bi] = vbn; }

    for (int i = 0; i < NX; i += 4) {
        float wu[4], wr[4], wn[4];
#pragma unroll
        for (int c = 0; c < 4; c++) {
            int wi = (2 * NH + i + c) * 100 + j;
            wu[c] = __ldg(Wu1 + wi);
            wr[c] = __ldg(Wr1 + wi);
            wn[c] = __ldg(Wn1 + wi);
        }
#pragma unroll
        for (int bi = 0; bi < 8; bi++) {
            float4 xv = *reinterpret_cast<const float4*>(
                x + ((size_t)(b0 + bi) * NT + t) * NX + i);
            au[bi] += xv.x * wu[0] + xv.y * wu[1] + xv.z * wu[2] + xv.w * wu[3];
            ar[bi] += xv.x * wr[0] + xv.y * wr[1] + xv.z * wr[2] + xv.w * wr[3];
            an[bi] += xv.x * wn[0] + xv.y * wn[1] + xv.z * wn[2] + xv.w * wn[3];
        }
    }
#pragma unroll
    for (int bi = 0; bi < 8; bi++) {
        int idx = (t * NB + b0 + bi) * 100 + j;
        g_xpu[idx] = au[bi];
        g_xpr[idx] = ar[bi];
        g_xpn[idx] = an[bi];
    }
}

__device__ __forceinline__ float sigm(float v) {
    return 1.0f / (1.0f + expf(-v));
}

// ---------------------------------------------------------------------------
// Persistent recurrent kernel: 128 blocks x 256 threads.
// Block bx owns batch rows 2bx, 2bx+1 for all 200 steps + final head.
// ---------------------------------------------------------------------------
__global__ __launch_bounds__(256) void odegru_kernel(
    const float* __restrict__ xt,
    const float* __restrict__ Wu1, const float* __restrict__ Wu2, const float* __restrict__ bu2,
    const float* __restrict__ Wr1, const float* __restrict__ Wr2, const float* __restrict__ br2,
    const float* __restrict__ Wn1, const float* __restrict__ Wn2, const float* __restrict__ bn2,
    const float* __restrict__ Wo1, const float* __restrict__ bo1,
    const float* __restrict__ Wo2, const float* __restrict__ bo2,
    const float* __restrict__ Wt1, const float* __restrict__ bt1,
    const float* __restrict__ Wt2, const float* __restrict__ bt2,
    const float* __restrict__ Wt3, const float* __restrict__ bt3,
    float* __restrict__ out)
{
    __shared__ __align__(16) float sh_h [2][NH];
    __shared__ __align__(16) float sh_hs[2][NH];
    __shared__ __align__(16) float sh_ho[2][NH];
    __shared__ __align__(16) float sh_u [2][NH];
    __shared__ __align__(16) float sh_ch[2][NH];
    __shared__ __align__(16) float sh_cs[2][NH];
    __shared__ __align__(16) float sh_t1[2][100];
    __shared__ __align__(16) float sh_t2[2][100];
    __shared__ __align__(16) float sh_part[8][4][100];

    const int tid = threadIdx.x;
    const int b0  = blockIdx.x * 2;

    // split-k mapping (phase-1 GEMMs), valid for tid < 200
    const int g = tid % 25;        // j-group: columns 4g..4g+3
    const int c = tid / 25;        // k-chunk 0..7
    // reduce mapping, valid for tid < 200
    const int rrow = tid / 100, rj = tid % 100;
    // phase-2 mapping (all 256 threads)
    const int row2 = tid >> 7;
    const int k4   = (tid & 127) * 4;

    // init states to zero
    for (int k = tid; k < NH; k += 256) {
        sh_h[0][k] = 0.f; sh_h[1][k] = 0.f;
        sh_hs[0][k] = 0.f; sh_hs[1][k] = 0.f;
    }
    __syncthreads();

    for (int t = 0; t < NT; t++) {
        float dt;
        if (t == 0)      dt = -0.01f;
        else if (t == 1) dt = xt[NT - 1] - xt[0];
        else             dt = xt[t - 2] - xt[t - 1];

        // ---- Phase A1: a = tanh(h @ Wo1 + bo1), split-k (chunks of 64) ----
        if (tid < 200) {
            float4 a0 = {0.f,0.f,0.f,0.f}, a1 = {0.f,0.f,0.f,0.f};
            const float* wp = Wo1 + (c * 64) * 100 + 4 * g;
            const float* s0 = &sh_h[0][c * 64];
            const float* s1 = &sh_h[1][c * 64];
#pragma unroll 4
            for (int kc = 0; kc < 64; kc++) {
                float4 w = *reinterpret_cast<const float4*>(wp); wp += 100;
                float v0 = s0[kc], v1 = s1[kc];
                a0.x += v0 * w.x; a0.y += v0 * w.y; a0.z += v0 * w.z; a0.w += v0 * w.w;
                a1.x += v1 * w.x; a1.y += v1 * w.y; a1.z += v1 * w.z; a1.w += v1 * w.w;
            }
            *reinterpret_cast<float4*>(&sh_part[c][0][4 * g]) = a0;
            *reinterpret_cast<float4*>(&sh_part[c][1][4 * g]) = a1;
        }
        __syncthreads();
        if (tid < 200) {
            float s = bo1[rj];
#pragma unroll
            for (int cc = 0; cc < 8; cc++) s += sh_part[cc][rrow][rj];
            sh_t1[rrow][rj] = tanhf(s);
        }
        __syncthreads();

        // ---- Phase A2: h_ode = h + dt * (a @ Wo2 + bo2) ----
        {
            float4 acc = *reinterpret_cast<const float4*>(bo2 + k4);
            const float* wp = Wo2 + k4;
#pragma unroll 4
            for (int j = 0; j < 100; j++) {
                float4 w = *reinterpret_cast<const float4*>(wp); wp += NH;
                float av = sh_t1[row2][j];
                acc.x += av * w.x; acc.y += av * w.y; acc.z += av * w.z; acc.w += av * w.w;
            }
            float4 hv = *reinterpret_cast<float4*>(&sh_h[row2][k4]);
            float4 ho;
            ho.x = hv.x + dt * acc.x; ho.y = hv.y + dt * acc.y;
            ho.z = hv.z + dt * acc.z; ho.w = hv.w + dt * acc.w;
            *reinterpret_cast<float4*>(&sh_ho[row2][k4]) = ho;
        }
        __syncthreads();

        // ---- Phase B1: tu/tr = tanh(xp + [ho,hs] @ W{u,r}1[0:1024]), split-k ----
        if (tid < 200) {
            float4 au0 = {0.f,0.f,0.f,0.f}, au1 = {0.f,0.f,0.f,0.f};
            float4 ar0 = {0.f,0.f,0.f,0.f}, ar1 = {0.f,0.f,0.f,0.f};
            const int kk0 = c * 128;
            const float* wu = Wu1 + kk0 * 100 + 4 * g;
            const float* wr = Wr1 + kk0 * 100 + 4 * g;
            const float *sp0, *sp1;
            if (c < 4) { sp0 = &sh_ho[0][kk0];      sp1 = &sh_ho[1][kk0]; }
            else       { sp0 = &sh_hs[0][kk0 - NH]; sp1 = &sh_hs[1][kk0 - NH]; }
#pragma unroll 4
            for (int kc = 0; kc < 128; kc++) {
                float4 wuv = *reinterpret_cast<const float4*>(wu); wu += 100;
                float4 wrv = *reinterpret_cast<const float4*>(wr); wr += 100;
                float v0 = sp0[kc], v1 = sp1[kc];
                au0.x += v0 * wuv.x; au0.y += v0 * wuv.y; au0.z += v0 * wuv.z; au0.w += v0 * wuv.w;
                au1.x += v1 * wuv.x; au1.y += v1 * wuv.y; au1.z += v1 * wuv.z; au1.w += v1 * wuv.w;
                ar0.x += v0 * wrv.x; ar0.y += v0 * wrv.y; ar0.z += v0 * wrv.z; ar0.w += v0 * wrv.w;
                ar1.x += v1 * wrv.x; ar1.y += v1 * wrv.y; ar1.z += v1 * wrv.z; ar1.w += v1 * wrv.w;
            }
            *reinterpret_cast<float4*>(&sh_part[c][0][4 * g]) = au0;
            *reinterpret_cast<float4*>(&sh_part[c][1][4 * g]) = au1;
            *reinterpret_cast<float4*>(&sh_part[c][2][4 * g]) = ar0;
            *reinterpret_cast<float4*>(&sh_part[c][3][4 * g]) = ar1;
        }
        __syncthreads();
        if (tid < 200) {
            int idx = (t * NB + b0 + rrow) * 100 + rj;
            float su = g_xpu[idx], sr = g_xpr[idx];
#pragma unroll
            for (int cc = 0; cc < 8; cc++) {
                su += sh_part[cc][rrow][rj];
                sr += sh_part[cc][2 + rrow][rj];
            }
            sh_t1[rrow][rj] = tanhf(su);
            sh_t2[rrow][rj] = tanhf(sr);
        }
        __syncthreads();

        // ---- Phase B2: u = sigm(tu@Wu2+bu2), r = sigm(tr@Wr2+br2); c-vectors ----
        {
            float4 accu = *reinterpret_cast<const float4*>(bu2 + k4);
            float4 accr = *reinterpret_cast<const float4*>(br2 + k4);
            const float* wu = Wu2 + k4;
            const float* wr = Wr2 + k4;
#pragma unroll 4
            for (int j = 0; j < 100; j++) {
                float4 wuv = *reinterpret_cast<const float4*>(wu); wu += NH;
                float4 wrv = *reinterpret_cast<const float4*>(wr); wr += NH;
                float tu = sh_t1[row2][j], tr = sh_t2[row2][j];
                accu.x += tu * wuv.x; accu.y += tu * wuv.y; accu.z += tu * wuv.z; accu.w += tu * wuv.w;
                accr.x += tr * wrv.x; accr.y += tr * wrv.y; accr.z += tr * wrv.z; accr.w += tr * wrv.w;
            }
            float4 u, r;
            u.x = sigm(accu.x); u.y = sigm(accu.y); u.z = sigm(accu.z); u.w = sigm(accu.w);
            r.x = sigm(accr.x); r.y = sigm(accr.y); r.z = sigm(accr.z); r.w = sigm(accr.w);
            *reinterpret_cast<float4*>(&sh_u[row2][k4]) = u;
            float4 ho = *reinterpret_cast<float4*>(&sh_ho[row2][k4]);
            float4 hs = *reinterpret_cast<float4*>(&sh_hs[row2][k4]);
            float4 ch, cs;
            ch.x = ho.x * r.x; ch.y = ho.y * r.y; ch.z = ho.z * r.z; ch.w = ho.w * r.w;
            cs.x = hs.x * r.x; cs.y = hs.y * r.y; cs.z = hs.z * r.z; cs.w = hs.w * r.w;
            *reinterpret_cast<float4*>(&sh_ch[row2][k4]) = ch;
            *reinterpret_cast<float4*>(&sh_cs[row2][k4]) = cs;
        }
        __syncthreads();

        // ---- Phase C1: tn = tanh(xpn + [ch,cs] @ Wn1[0:1024]), split-k ----
        if (tid < 200) {
            float4 a0 = {0.f,0.f,0.f,0.f}, a1 = {0.f,0.f,0.f,0.f};
            const int kk0 = c * 128;
            const float* wn = Wn1 + kk0 * 100 + 4 * g;
            const float *sp0, *sp1;
            if (c < 4) { sp0 = &sh_ch[0][kk0];      sp1 = &sh_ch[1][kk0]; }
            else       { sp0 = &sh_cs[0][kk0 - NH]; sp1 = &sh_cs[1][kk0 - NH]; }
#pragma unroll 4
            for (int kc = 0; kc < 128; kc++) {
                float4 w = *reinterpret_cast<const float4*>(wn); wn += 100;
                float v0 = sp0[kc], v1 = sp1[kc];
                a0.x += v0 * w.x; a0.y += v0 * w.y; a0.z += v0 * w.z; a0.w += v0 * w.w;
                a1.x += v1 * w.x; a1.y += v1 * w.y; a1.z += v1 * w.z; a1.w += v1 * w.w;
            }
            *reinterpret_cast<float4*>(&sh_part[c][0][4 * g]) = a0;
            *reinterpret_cast<float4*>(&sh_part[c][1][4 * g]) = a1;
        }
        __syncthreads();
        if (tid < 200) {
            int idx = (t * NB + b0 + rrow) * 100 + rj;
            float sn = g_xpn[idx];
#pragma unroll
            for (int cc = 0; cc < 8; cc++) sn += sh_part[cc][rrow][rj];
            sh_t1[rrow][rj] = tanhf(sn);
        }
        __syncthreads();

        // ---- Phase C2: ns = tn @ Wn2 + bn2; state update ----
        {
            float4 am = *reinterpret_cast<const float4*>(bn2 + k4);
            float4 as = *reinterpret_cast<const float4*>(bn2 + NH + k4);
            const float* wm = Wn2 + k4;
            const float* ws = Wn2 + NH + k4;
#pragma unroll 4
            for (int j = 0; j < 100; j++) {
                float4 wmv = *reinterpret_cast<const float4*>(wm); wm += 2 * NH;
                float4 wsv = *reinterpret_cast<const float4*>(ws); ws += 2 * NH;
                float tn = sh_t1[row2][j];
                am.x += tn * wmv.x; am.y += tn * wmv.y; am.z += tn * wmv.z; am.w += tn * wmv.w;
                as.x += tn * wsv.x; as.y += tn * wsv.y; as.z += tn * wsv.z; as.w += tn * wsv.w;
            }
            float4 u  = *reinterpret_cast<float4*>(&sh_u [row2][k4]);
            float4 ho = *reinterpret_cast<float4*>(&sh_ho[row2][k4]);
            float4 hs = *reinterpret_cast<float4*>(&sh_hs[row2][k4]);
            float4 hn, sn;
            hn.x = (1.f - u.x) * am.x + u.x * ho.x;
            hn.y = (1.f - u.y) * am.y + u.y * ho.y;
            hn.z = (1.f - u.z) * am.z + u.z * ho.z;
            hn.w = (1.f - u.w) * am.w + u.w * ho.w;
            sn.x = (1.f - u.x) * fabsf(as.x) + u.x * hs.x;
            sn.y = (1.f - u.y) * fabsf(as.y) + u.y * hs.y;
            sn.z = (1.f - u.z) * fabsf(as.z) + u.z * hs.z;
            sn.w = (1.f - u.w) * fabsf(as.w) + u.w * hs.w;
            *reinterpret_cast<float4*>(&sh_h [row2][k4]) = hn;
            *reinterpret_cast<float4*>(&sh_hs[row2][k4]) = sn;
        }
        __syncthreads();
    }

    // ================= Final head =================
    // z1 = tanh([h, hs] @ Wt1 + bt1)
    if (tid < 200) {
        float4 a0 = {0.f,0.f,0.f,0.f}, a1 = {0.f,0.f,0.f,0.f};
        const int kk0 = c * 128;
        const float* w = Wt1 + kk0 * 100 + 4 * g;
        const float *sp0, *sp1;
        if (c < 4) { sp0 = &sh_h[0][kk0];       sp1 = &sh_h[1][kk0]; }
        else       { sp0 = &sh_hs[0][kk0 - NH]; sp1 = &sh_hs[1][kk0 - NH]; }
#pragma unroll 4
        for (int kc = 0; kc < 128; kc++) {
            float4 wv = *reinterpret_cast<const float4*>(w); w += 100;
            float v0 = sp0[kc], v1 = sp1[kc];
            a0.x += v0 * wv.x; a0.y += v0 * wv.y; a0.z += v0 * wv.z; a0.w += v0 * wv.w;
            a1.x += v1 * wv.x; a1.y += v1 * wv.y; a1.z += v1 * wv.z; a1.w += v1 * wv.w;
        }
        *reinterpret_cast<float4*>(&sh_part[c][0][4 * g]) = a0;
        *reinterpret_cast<float4*>(&sh_part[c][1][4 * g]) = a1;
    }
    __syncthreads();
    if (tid < 200) {
        float s = bt1[rj];
#pragma unroll
        for (int cc = 0; cc < 8; cc++) s += sh_part[cc][rrow][rj];
        sh_t1[rrow][rj] = tanhf(s);
    }
    __syncthreads();
    // z2 = tanh(z1 @ Wt2 + bt2)
    if (tid < 200) {
        float s = bt2[rj];
#pragma unroll 4
        for (int jj = 0; jj < 100; jj++) s += sh_t1[rrow][jj] * Wt2[jj * 100 + rj];
        sh_t2[rrow][rj] = tanhf(s);
    }
    __syncthreads();
    // z3 = z2 @ Wt3 + bt3; mu / sigma out
    {
        float4 am = *reinterpret_cast<const float4*>(bt3 + k4);
        float4 as = *reinterpret_cast<const float4*>(bt3 + NH + k4);
        const float* wm = Wt3 + k4;
        const float* ws = Wt3 + NH + k4;
#pragma unroll 4
        for (int j = 0; j < 100; j++) {
            float4 wmv = *reinterpret_cast<const float4*>(wm); wm += 2 * NH;
            float4 wsv = *reinterpret_cast<const float4*>(ws); ws += 2 * NH;
            float z = sh_t2[row2][j];
            am.x += z * wmv.x; am.y += z * wmv.y; am.z += z * wmv.z; am.w += z * wmv.w;
            as.x += z * wsv.x; as.y += z * wsv.y; as.z += z * wsv.z; as.w += z * wsv.w;
        }
        float4 sg;
        sg.x = fabsf(as.x); sg.y = fabsf(as.y); sg.z = fabsf(as.z); sg.w = fabsf(as.w);
        int rowg = b0 + row2;
        *reinterpret_cast<float4*>(out + (size_t)rowg * NH + k4) = am;
        *reinterpret_cast<float4*>(out + (size_t)NB * NH + (size_t)rowg * NH + k4) = sg;
    }
}

// ---------------------------------------------------------------------------
extern "C" void kernel_launch(void* const* d_in, const int* in_sizes, int n_in,
                              void* d_out, int out_size) {
    const float* x   = (const float*)d_in[0];
    const float* xt  = (const float*)d_in[1];
    const float* Wu1 = (const float*)d_in[2];
    const float* bu1 = (const float*)d_in[3];
    const float* Wu2 = (const float*)d_in[4];
    const float* bu2 = (const float*)d_in[5];
    const float* Wr1 = (const float*)d_in[6];
    const float* br1 = (const float*)d_in[7];
    const float* Wr2 = (const float*)d_in[8];
    const float* br2 = (const float*)d_in[9];
    const float* Wn1 = (const float*)d_in[10];
    const float* bn1 = (const float*)d_in[11];
    const float* Wn2 = (const float*)d_in[12];
    const float* bn2 = (const float*)d_in[13];
    const float* Wo1 = (const float*)d_in[14];
    const float* bo1 = (const float*)d_in[15];
    const float* Wo2 = (const float*)d_in[16];
    const float* bo2 = (const float*)d_in[17];
    const float* Wt1 = (const float*)d_in[18];
    const float* bt1 = (const float*)d_in[19];
    const float* Wt2 = (const float*)d_in[20];
    const float* bt2 = (const float*)d_in[21];
    const float* Wt3 = (const float*)d_in[22];
    const float* bt3 = (const float*)d_in[23];
    float* out = (float*)d_out;

    dim3 pgrid(NT, 16);
    prep_xproj_kernel<<<pgrid, 256>>>(x, Wu1, bu1, Wr1, br1, Wn1, bn1);
    odegru_kernel<<<NB / 2, 256>>>(xt,
        Wu1, Wu2, bu2, Wr1, Wr2, br2, Wn1, Wn2, bn2,
        Wo1, bo1, Wo2, bo2, Wt1, bt1, Wt2, bt2, Wt3, bt3, out);
}

// round 6
// speedup vs baseline: 2.0109x; 2.0109x over previous
#include <cuda_runtime.h>
#include <math.h>

// Problem constants: B=256, T=200, X=128, H=512, NU=100, cin=1152.
#define NB 256
#define NT 200
#define NX 128
#define NH 512
#define NTH 512

// Device-global scratch (allocation-free): x-projections with bias folded.
// Layout [t][b][j], j in [0,100).
__device__ float g_xpu[NT * NB * 100];
__device__ float g_xpr[NT * NB * 100];
__device__ float g_xpn[NT * NB * 100];

// ---------------------------------------------------------------------------
// Prep: g_xp*[t][b][j] = b*1[j] + sum_i x[b][t][i] * W*1[(1024+i)*100 + j]
// ---------------------------------------------------------------------------
__global__ __launch_bounds__(256) void prep_xproj_kernel(
    const float* __restrict__ x,
    const float* __restrict__ Wu1, const float* __restrict__ bu1,
    const float* __restrict__ Wr1, const float* __restrict__ br1,
    const float* __restrict__ Wn1, const float* __restrict__ bn1)
{
    int t   = blockIdx.x;          // 0..199
    int bt  = blockIdx.y;          // 0..15
    int tid = threadIdx.x;
    if (tid >= 200) return;
    int j  = tid % 100;
    int s  = tid / 100;            // 0 or 1
    int b0 = bt * 16 + s * 8;

    float au[8], ar[8], an[8];
    float vbu = bu1[j], vbr = br1[j], vbn = bn1[j];
#pragma unroll
    for (int bi = 0; bi < 8; bi++) { au[bi] = vbu; ar[bi] = vbr; an[bi] = vbn; }

    for (int i = 0; i < NX; i += 4) {
        float wu[4], wr[4], wn[4];
#pragma unroll
        for (int c = 0; c < 4; c++) {
            int wi = (2 * NH + i + c) * 100 + j;
            wu[c] = __ldg(Wu1 + wi);
            wr[c] = __ldg(Wr1 + wi);
            wn[c] = __ldg(Wn1 + wi);
        }
#pragma unroll
        for (int bi = 0; bi < 8; bi++) {
            float4 xv = *reinterpret_cast<const float4*>(
                x + ((size_t)(b0 + bi) * NT + t) * NX + i);
            au[bi] += xv.x * wu[0] + xv.y * wu[1] + xv.z * wu[2] + xv.w * wu[3];
            ar[bi] += xv.x * wr[0] + xv.y * wr[1] + xv.z * wr[2] + xv.w * wr[3];
            an[bi] += xv.x * wn[0] + xv.y * wn[1] + xv.z * wn[2] + xv.w * wn[3];
        }
    }
#pragma unroll
    for (int bi = 0; bi < 8; bi++) {
        int idx = (t * NB + b0 + bi) * 100 + j;
        g_xpu[idx] = au[bi];
        g_xpr[idx] = ar[bi];
        g_xpn[idx] = an[bi];
    }
}

__device__ __forceinline__ float fast_tanh(float x) {
    float y;
    asm("tanh.approx.f32 %0, %1;" : "=f"(y) : "f"(x));
    return y;
}
__device__ __forceinline__ float sigm(float v) {
    return 0.5f * fast_tanh(0.5f * v) + 0.5f;
}

// ---------------------------------------------------------------------------
// Persistent recurrent kernel: 128 blocks x 512 threads (16 warps/SM).
// Block bx owns batch rows 2bx, 2bx+1 for all 200 steps + final head.
// ---------------------------------------------------------------------------
__global__ __launch_bounds__(NTH) void odegru_kernel(
    const float* __restrict__ xt,
    const float* __restrict__ Wu1, const float* __restrict__ Wu2, const float* __restrict__ bu2,
    const float* __restrict__ Wr1, const float* __restrict__ Wr2, const float* __restrict__ br2,
    const float* __restrict__ Wn1, const float* __restrict__ Wn2, const float* __restrict__ bn2,
    const float* __restrict__ Wo1, const float* __restrict__ bo1,
    const float* __restrict__ Wo2, const float* __restrict__ bo2,
    const float* __restrict__ Wt1, const float* __restrict__ bt1,
    const float* __restrict__ Wt2, const float* __restrict__ bt2,
    const float* __restrict__ Wt3, const float* __restrict__ bt3,
    float* __restrict__ out)
{
    __shared__ __align__(16) float sh_h [2][NH];
    __shared__ __align__(16) float sh_hs[2][NH];
    __shared__ __align__(16) float sh_ho[2][NH];
    __shared__ __align__(16) float sh_u [2][NH];
    __shared__ __align__(16) float sh_ch[2][NH];
    __shared__ __align__(16) float sh_cs[2][NH];
    __shared__ __align__(16) float sh_t1[2][100];
    __shared__ __align__(16) float sh_t2[2][100];
    __shared__ __align__(16) float sh_part[16][4][100];

    const int tid = threadIdx.x;
    const int b0  = blockIdx.x * 2;

    // phase-1 split-k mapping (valid for tid < 400): 16 k-chunks x 25 j-groups
    const int g = tid % 25;        // j-group: columns 4g..4g+3
    const int c = tid / 25;        // k-chunk 0..15
    // reduce mappings
    const int rrow = (tid / 100) & 1, rj = tid % 100;   // for tid < 200 / < 400
    const int rgate = tid / 200;                         // 0=u, 1=r (tid < 400)
    // phase-2 mapping (all 512 threads): one row, 2 cols
    const int row2 = tid >> 8;          // 0 or 1
    const int k2   = (tid & 255) * 2;   // 0..510

    // init states to zero
    for (int k = tid; k < NH; k += NTH) {
        sh_h[0][k] = 0.f; sh_h[1][k] = 0.f;
        sh_hs[0][k] = 0.f; sh_hs[1][k] = 0.f;
    }
    __syncthreads();

    for (int t = 0; t < NT; t++) {
        float dt;
        if (t == 0)      dt = -0.01f;
        else if (t == 1) dt = xt[NT - 1] - xt[0];
        else             dt = xt[t - 2] - xt[t - 1];

        // ---- Phase A1: a = tanh(h @ Wo1 + bo1), split-k (16 chunks of 32) ----
        if (tid < 400) {
            float4 a0 = {0.f,0.f,0.f,0.f}, a1 = {0.f,0.f,0.f,0.f};
            const float* wp = Wo1 + (c * 32) * 100 + 4 * g;
            const float* s0 = &sh_h[0][c * 32];
            const float* s1 = &sh_h[1][c * 32];
#pragma unroll 8
            for (int kc = 0; kc < 32; kc++) {
                float4 w = *reinterpret_cast<const float4*>(wp); wp += 100;
                float v0 = s0[kc], v1 = s1[kc];
                a0.x += v0 * w.x; a0.y += v0 * w.y; a0.z += v0 * w.z; a0.w += v0 * w.w;
                a1.x += v1 * w.x; a1.y += v1 * w.y; a1.z += v1 * w.z; a1.w += v1 * w.w;
            }
            *reinterpret_cast<float4*>(&sh_part[c][0][4 * g]) = a0;
            *reinterpret_cast<float4*>(&sh_part[c][1][4 * g]) = a1;
        }
        __syncthreads();
        if (tid < 200) {
            float s = bo1[rj];
#pragma unroll
            for (int cc = 0; cc < 16; cc++) s += sh_part[cc][rrow][rj];
            sh_t1[rrow][rj] = fast_tanh(s);
        }
        __syncthreads();

        // ---- Phase A2: h_ode = h + dt * (a @ Wo2 + bo2) ----
        {
            float2 acc = *reinterpret_cast<const float2*>(bo2 + k2);
            const float* wp = Wo2 + k2;
#pragma unroll 8
            for (int j = 0; j < 100; j++) {
                float2 w = *reinterpret_cast<const float2*>(wp); wp += NH;
                float av = sh_t1[row2][j];
                acc.x += av * w.x; acc.y += av * w.y;
            }
            float2 hv = *reinterpret_cast<float2*>(&sh_h[row2][k2]);
            float2 ho;
            ho.x = hv.x + dt * acc.x; ho.y = hv.y + dt * acc.y;
            *reinterpret_cast<float2*>(&sh_ho[row2][k2]) = ho;
        }
        __syncthreads();

        // ---- Phase B1: tu/tr = tanh(xp + [ho,hs] @ W{u,r}1[0:1024]), split-k ----
        if (tid < 400) {
            float4 au0 = {0.f,0.f,0.f,0.f}, au1 = {0.f,0.f,0.f,0.f};
            float4 ar0 = {0.f,0.f,0.f,0.f}, ar1 = {0.f,0.f,0.f,0.f};
            const int kk0 = c * 64;
            const float* wu = Wu1 + kk0 * 100 + 4 * g;
            const float* wr = Wr1 + kk0 * 100 + 4 * g;
            const float *sp0, *sp1;
            if (c < 8) { sp0 = &sh_ho[0][kk0];      sp1 = &sh_ho[1][kk0]; }
            else       { sp0 = &sh_hs[0][kk0 - NH]; sp1 = &sh_hs[1][kk0 - NH]; }
#pragma unroll 8
            for (int kc = 0; kc < 64; kc++) {
                float4 wuv = *reinterpret_cast<const float4*>(wu); wu += 100;
                float4 wrv = *reinterpret_cast<const float4*>(wr); wr += 100;
                float v0 = sp0[kc], v1 = sp1[kc];
                au0.x += v0 * wuv.x; au0.y += v0 * wuv.y; au0.z += v0 * wuv.z; au0.w += v0 * wuv.w;
                au1.x += v1 * wuv.x; au1.y += v1 * wuv.y; au1.z += v1 * wuv.z; au1.w += v1 * wuv.w;
                ar0.x += v0 * wrv.x; ar0.y += v0 * wrv.y; ar0.z += v0 * wrv.z; ar0.w += v0 * wrv.w;
                ar1.x += v1 * wrv.x; ar1.y += v1 * wrv.y; ar1.z += v1 * wrv.z; ar1.w += v1 * wrv.w;
            }
            *reinterpret_cast<float4*>(&sh_part[c][0][4 * g]) = au0;
            *reinterpret_cast<float4*>(&sh_part[c][1][4 * g]) = au1;
            *reinterpret_cast<float4*>(&sh_part[c][2][4 * g]) = ar0;
            *reinterpret_cast<float4*>(&sh_part[c][3][4 * g]) = ar1;
        }
        __syncthreads();
        if (tid < 400) {
            int idx = (t * NB + b0 + rrow) * 100 + rj;
            if (rgate == 0) {
                float su = g_xpu[idx];
#pragma unroll
                for (int cc = 0; cc < 16; cc++) su += sh_part[cc][rrow][rj];
                sh_t1[rrow][rj] = fast_tanh(su);
            } else {
                float sr = g_xpr[idx];
#pragma unroll
                for (int cc = 0; cc < 16; cc++) sr += sh_part[cc][2 + rrow][rj];
                sh_t2[rrow][rj] = fast_tanh(sr);
            }
        }
        __syncthreads();

        // ---- Phase B2: u = sigm(tu@Wu2+bu2), r = sigm(tr@Wr2+br2); c-vectors ----
        {
            float2 accu = *reinterpret_cast<const float2*>(bu2 + k2);
            float2 accr = *reinterpret_cast<const float2*>(br2 + k2);
            const float* wu = Wu2 + k2;
            const float* wr = Wr2 + k2;
#pragma unroll 8
            for (int j = 0; j < 100; j++) {
                float2 wuv = *reinterpret_cast<const float2*>(wu); wu += NH;
                float2 wrv = *reinterpret_cast<const float2*>(wr); wr += NH;
                float tu = sh_t1[row2][j], tr = sh_t2[row2][j];
                accu.x += tu * wuv.x; accu.y += tu * wuv.y;
                accr.x += tr * wrv.x; accr.y += tr * wrv.y;
            }
            float2 u, r;
            u.x = sigm(accu.x); u.y = sigm(accu.y);
            r.x = sigm(accr.x); r.y = sigm(accr.y);
            *reinterpret_cast<float2*>(&sh_u[row2][k2]) = u;
            float2 ho = *reinterpret_cast<float2*>(&sh_ho[row2][k2]);
            float2 hs = *reinterpret_cast<float2*>(&sh_hs[row2][k2]);
            float2 ch, cs;
            ch.x = ho.x * r.x; ch.y = ho.y * r.y;
            cs.x = hs.x * r.x; cs.y = hs.y * r.y;
            *reinterpret_cast<float2*>(&sh_ch[row2][k2]) = ch;
            *reinterpret_cast<float2*>(&sh_cs[row2][k2]) = cs;
        }
        __syncthreads();

        // ---- Phase C1: tn = tanh(xpn + [ch,cs] @ Wn1[0:1024]), split-k ----
        if (tid < 400) {
            float4 a0 = {0.f,0.f,0.f,0.f}, a1 = {0.f,0.f,0.f,0.f};
            const int kk0 = c * 64;
            const float* wn = Wn1 + kk0 * 100 + 4 * g;
            const float *sp0, *sp1;
            if (c < 8) { sp0 = &sh_ch[0][kk0];      sp1 = &sh_ch[1][kk0]; }
            else       { sp0 = &sh_cs[0][kk0 - NH]; sp1 = &sh_cs[1][kk0 - NH]; }
#pragma unroll 8
            for (int kc = 0; kc < 64; kc++) {
                float4 w = *reinterpret_cast<const float4*>(wn); wn += 100;
                float v0 = sp0[kc], v1 = sp1[kc];
                a0.x += v0 * w.x; a0.y += v0 * w.y; a0.z += v0 * w.z; a0.w += v0 * w.w;
                a1.x += v1 * w.x; a1.y += v1 * w.y; a1.z += v1 * w.z; a1.w += v1 * w.w;
            }
            *reinterpret_cast<float4*>(&sh_part[c][0][4 * g]) = a0;
            *reinterpret_cast<float4*>(&sh_part[c][1][4 * g]) = a1;
        }
        __syncthreads();
        if (tid < 200) {
            int idx = (t * NB + b0 + rrow) * 100 + rj;
            float sn = g_xpn[idx];
#pragma unroll
            for (int cc = 0; cc < 16; cc++) sn += sh_part[cc][rrow][rj];
            sh_t1[rrow][rj] = fast_tanh(sn);
        }
        __syncthreads();

        // ---- Phase C2: ns = tn @ Wn2 + bn2; state update ----
        {
            float2 am = *reinterpret_cast<const float2*>(bn2 + k2);
            float2 as = *reinterpret_cast<const float2*>(bn2 + NH + k2);
            const float* wm = Wn2 + k2;
            const float* ws = Wn2 + NH + k2;
#pragma unroll 8
            for (int j = 0; j < 100; j++) {
                float2 wmv = *reinterpret_cast<const float2*>(wm); wm += 2 * NH;
                float2 wsv = *reinterpret_cast<const float2*>(ws); ws += 2 * NH;
                float tn = sh_t1[row2][j];
                am.x += tn * wmv.x; am.y += tn * wmv.y;
                as.x += tn * wsv.x; as.y += tn * wsv.y;
            }
            float2 u  = *reinterpret_cast<float2*>(&sh_u [row2][k2]);
            float2 ho = *reinterpret_cast<float2*>(&sh_ho[row2][k2]);
            float2 hs = *reinterpret_cast<float2*>(&sh_hs[row2][k2]);
            float2 hn, sn;
            hn.x = (1.f - u.x) * am.x + u.x * ho.x;
            hn.y = (1.f - u.y) * am.y + u.y * ho.y;
            sn.x = (1.f - u.x) * fabsf(as.x) + u.x * hs.x;
            sn.y = (1.f - u.y) * fabsf(as.y) + u.y * hs.y;
            *reinterpret_cast<float2*>(&sh_h [row2][k2]) = hn;
            *reinterpret_cast<float2*>(&sh_hs[row2][k2]) = sn;
        }
        __syncthreads();
    }

    // ================= Final head =================
    // z1 = tanh([h, hs] @ Wt1 + bt1)
    if (tid < 400) {
        float4 a0 = {0.f,0.f,0.f,0.f}, a1 = {0.f,0.f,0.f,0.f};
        const int kk0 = c * 64;
        const float* w = Wt1 + kk0 * 100 + 4 * g;
        const float *sp0, *sp1;
        if (c < 8) { sp0 = &sh_h[0][kk0];       sp1 = &sh_h[1][kk0]; }
        else       { sp0 = &sh_hs[0][kk0 - NH]; sp1 = &sh_hs[1][kk0 - NH]; }
#pragma unroll 8
        for (int kc = 0; kc < 64; kc++) {
            float4 wv = *reinterpret_cast<const float4*>(w); w += 100;
            float v0 = sp0[kc], v1 = sp1[kc];
            a0.x += v0 * wv.x; a0.y += v0 * wv.y; a0.z += v0 * wv.z; a0.w += v0 * wv.w;
            a1.x += v1 * wv.x; a1.y += v1 * wv.y; a1.z += v1 * wv.z; a1.w += v1 * wv.w;
        }
        *reinterpret_cast<float4*>(&sh_part[c][0][4 * g]) = a0;
        *reinterpret_cast<float4*>(&sh_part[c][1][4 * g]) = a1;
    }
    __syncthreads();
    if (tid < 200) {
        float s = bt1[rj];
#pragma unroll
        for (int cc = 0; cc < 16; cc++) s += sh_part[cc][rrow][rj];
        sh_t1[rrow][rj] = tanhf(s);   // full-precision tanh for the head
    }
    __syncthreads();
    // z2 = tanh(z1 @ Wt2 + bt2)
    if (tid < 200) {
        float s = bt2[rj];
#pragma unroll 4
        for (int jj = 0; jj < 100; jj++) s += sh_t1[rrow][jj] * Wt2[jj * 100 + rj];
        sh_t2[rrow][rj] = tanhf(s);
    }
    __syncthreads();
    // z3 = z2 @ Wt3 + bt3; mu / sigma out
    {
        float2 am = *reinterpret_cast<const float2*>(bt3 + k2);
        float2 as = *reinterpret_cast<const float2*>(bt3 + NH + k2);
        const float* wm = Wt3 + k2;
        const float* ws = Wt3 + NH + k2;
#pragma unroll 8
        for (int j = 0; j < 100; j++) {
            float2 wmv = *reinterpret_cast<const float2*>(wm); wm += 2 * NH;
            float2 wsv = *reinterpret_cast<const float2*>(ws); ws += 2 * NH;
            float z = sh_t2[row2][j];
            am.x += z * wmv.x; am.y += z * wmv.y;
            as.x += z * wsv.x; as.y += z * wsv.y;
        }
        float2 sg;
        sg.x = fabsf(as.x); sg.y = fabsf(as.y);
        int rowg = b0 + row2;
        *reinterpret_cast<float2*>(out + (size_t)rowg * NH + k2) = am;
        *reinterpret_cast<float2*>(out + (size_t)NB * NH + (size_t)rowg * NH + k2) = sg;
    }
}

// ---------------------------------------------------------------------------
extern "C" void kernel_launch(void* const* d_in, const int* in_sizes, int n_in,
                              void* d_out, int out_size) {
    const float* x   = (const float*)d_in[0];
    const float* xt  = (const float*)d_in[1];
    const float* Wu1 = (const float*)d_in[2];
    const float* bu1 = (const float*)d_in[3];
    const float* Wu2 = (const float*)d_in[4];
    const float* bu2 = (const float*)d_in[5];
    const float* Wr1 = (const float*)d_in[6];
    const float* br1 = (const float*)d_in[7];
    const float* Wr2 = (const float*)d_in[8];
    const float* br2 = (const float*)d_in[9];
    const float* Wn1 = (const float*)d_in[10];
    const float* bn1 = (const float*)d_in[11];
    const float* Wn2 = (const float*)d_in[12];
    const float* bn2 = (const float*)d_in[13];
    const float* Wo1 = (const float*)d_in[14];
    const float* bo1 = (const float*)d_in[15];
    const float* Wo2 = (const float*)d_in[16];
    const float* bo2 = (const float*)d_in[17];
    const float* Wt1 = (const float*)d_in[18];
    const float* bt1 = (const float*)d_in[19];
    const float* Wt2 = (const float*)d_in[20];
    const float* bt2 = (const float*)d_in[21];
    const float* Wt3 = (const float*)d_in[22];
    const float* bt3 = (const float*)d_in[23];
    float* out = (float*)d_out;

    dim3 pgrid(NT, 16);
    prep_xproj_kernel<<<pgrid, 256>>>(x, Wu1, bu1, Wr1, br1, Wn1, bn1);
    odegru_kernel<<<NB / 2, NTH>>>(xt,
        Wu1, Wu2, bu2, Wr1, Wr2, br2, Wn1, Wn2, bn2,
        Wo1, bo1, Wo2, bo2, Wt1, bt1, Wt2, bt2, Wt3, bt3, out);
}

// round 8
// speedup vs baseline: 2.4956x; 1.2410x over previous
#include <cuda_runtime.h>
#include <math.h>

// Problem constants: B=256, T=200, X=128, H=512, NU=100, cin=1152.
#define NB 256
#define NT 200
#define NX 128
#define NH 512
#define NTH 1024

// Device-global scratch (allocation-free): x-projections with bias folded.
// Layout [t][b][j], j in [0,100).
__device__ float g_xpu[NT * NB * 100];
__device__ float g_xpr[NT * NB * 100];
__device__ float g_xpn[NT * NB * 100];

// ---------------------------------------------------------------------------
// Prep: g_xp*[t][b][j] = b*1[j] + sum_i x[b][t][i] * W*1[(1024+i)*100 + j]
// ---------------------------------------------------------------------------
__global__ __launch_bounds__(256) void prep_xproj_kernel(
    const float* __restrict__ x,
    const float* __restrict__ Wu1, const float* __restrict__ bu1,
    const float* __restrict__ Wr1, const float* __restrict__ br1,
    const float* __restrict__ Wn1, const float* __restrict__ bn1)
{
    int t   = blockIdx.x;          // 0..199
    int bt  = blockIdx.y;          // 0..15
    int tid = threadIdx.x;
    if (tid >= 200) return;
    int j  = tid % 100;
    int s  = tid / 100;            // 0 or 1
    int b0 = bt * 16 + s * 8;

    float au[8], ar[8], an[8];
    float vbu = bu1[j], vbr = br1[j], vbn = bn1[j];
#pragma unroll
    for (int bi = 0; bi < 8; bi++) { au[bi] = vbu; ar[bi] = vbr; an[bi] = vbn; }

    for (int i = 0; i < NX; i += 4) {
        float wu[4], wr[4], wn[4];
#pragma unroll
        for (int c = 0; c < 4; c++) {
            int wi = (2 * NH + i + c) * 100 + j;
            wu[c] = __ldg(Wu1 + wi);
            wr[c] = __ldg(Wr1 + wi);
            wn[c] = __ldg(Wn1 + wi);
        }
#pragma unroll
        for (int bi = 0; bi < 8; bi++) {
            float4 xv = *reinterpret_cast<const float4*>(
                x + ((size_t)(b0 + bi) * NT + t) * NX + i);
            au[bi] += xv.x * wu[0] + xv.y * wu[1] + xv.z * wu[2] + xv.w * wu[3];
            ar[bi] += xv.x * wr[0] + xv.y * wr[1] + xv.z * wr[2] + xv.w * wr[3];
            an[bi] += xv.x * wn[0] + xv.y * wn[1] + xv.z * wn[2] + xv.w * wn[3];
        }
    }
#pragma unroll
    for (int bi = 0; bi < 8; bi++) {
        int idx = (t * NB + b0 + bi) * 100 + j;
        g_xpu[idx] = au[bi];
        g_xpr[idx] = ar[bi];
        g_xpn[idx] = an[bi];
    }
}

__device__ __forceinline__ float fast_tanh(float x) {
    float y;
    asm("tanh.approx.f32 %0, %1;" : "=f"(y) : "f"(x));
    return y;
}
__device__ __forceinline__ float sigm(float v) {
    return 0.5f * fast_tanh(0.5f * v) + 0.5f;
}

// ---------------------------------------------------------------------------
// Persistent recurrent kernel: 128 blocks x 1024 threads (32 warps/SM).
// Block bx owns batch rows 2bx, 2bx+1 for all 200 steps + final head.
// ---------------------------------------------------------------------------
__global__ __launch_bounds__(NTH) void odegru_kernel(
    const float* __restrict__ xt,
    const float* __restrict__ Wu1, const float* __restrict__ Wu2, const float* __restrict__ bu2,
    const float* __restrict__ Wr1, const float* __restrict__ Wr2, const float* __restrict__ br2,
    const float* __restrict__ Wn1, const float* __restrict__ Wn2, const float* __restrict__ bn2,
    const float* __restrict__ Wo1, const float* __restrict__ bo1,
    const float* __restrict__ Wo2, const float* __restrict__ bo2,
    const float* __restrict__ Wt1, const float* __restrict__ bt1,
    const float* __restrict__ Wt2, const float* __restrict__ bt2,
    const float* __restrict__ Wt3, const float* __restrict__ bt3,
    float* __restrict__ out)
{
    __shared__ __align__(16) float sh_h [2][NH];
    __shared__ __align__(16) float sh_hs[2][NH];
    __shared__ __align__(16) float sh_ho[2][NH];
    __shared__ __align__(16) float sh_u [2][NH];
    __shared__ __align__(16) float sh_ch[2][NH];
    __shared__ __align__(16) float sh_cs[2][NH];
    __shared__ __align__(16) float sh_t1[2][100];
    __shared__ __align__(16) float sh_t2[2][100];
    // Phase-1 partials. Viewed as [32][2][100] (A1/C1/head) or [16][4][100] (B1).
    __shared__ __align__(16) float sh_part[32 * 2 * 100];
    __shared__ float sh_dt[NT];

    const int tid = threadIdx.x;
    const int b0  = blockIdx.x * 2;

    // split-k mapping for 800-thread phase-1 GEMMs
    const int g25 = tid % 25;           // j-group: cols 4g..4g+3
    const int c32 = tid / 25;           // chunk 0..31 (tid<800)
    // B1 mapping (tid<800): gate, then 16 chunks x 25 groups
    const int gateB = tid / 400;        // 0=u, 1=r
    const int sB    = tid % 400;
    const int cB    = sB / 25;          // 0..15
    const int gB    = sB % 25;
    // reduce mappings
    const int rrow  = (tid / 100) & 1, rj = tid % 100;  // tid<200 / tid<400
    const int rgate = tid / 200;                         // tid<400
    // phase-2 mappings
    const int rowA = tid >> 9;            // A2: 2 rows x 512 cols (scalar)
    const int colA = tid & 511;
    const int half = tid >> 9;            // B2/C2/H3: half split
    const int rem  = tid & 511;
    const int row2 = rem >> 8;
    const int k2   = (rem & 255) * 2;

    // init: dt table + zero states
    if (tid < NT) {
        float v;
        if (tid == 0)      v = -0.01f;
        else if (tid == 1) v = xt[NT - 1] - xt[0];
        else               v = xt[tid - 2] - xt[tid - 1];
        sh_dt[tid] = v;
    }
    for (int k = tid; k < NH; k += NTH) {
        sh_h[0][k] = 0.f; sh_h[1][k] = 0.f;
        sh_hs[0][k] = 0.f; sh_hs[1][k] = 0.f;
    }
    __syncthreads();

    for (int t = 0; t < NT; t++) {
        const float dt = sh_dt[t];

        // ---- Phase A1: a = tanh(h @ Wo1 + bo1); 32 chunks of 16 rows ----
        if (tid < 800) {
            float4 a0 = {0.f,0.f,0.f,0.f}, a1 = {0.f,0.f,0.f,0.f};
            const int kk0 = c32 * 16;
            const float* wp = Wo1 + kk0 * 100 + 4 * g25;
            const float* s0 = &sh_h[0][kk0];
            const float* s1 = &sh_h[1][kk0];
#pragma unroll
            for (int kc = 0; kc < 16; kc++) {
                float4 w = *reinterpret_cast<const float4*>(wp); wp += 100;
                float v0 = s0[kc], v1 = s1[kc];
                a0.x += v0 * w.x; a0.y += v0 * w.y; a0.z += v0 * w.z; a0.w += v0 * w.w;
                a1.x += v1 * w.x; a1.y += v1 * w.y; a1.z += v1 * w.z; a1.w += v1 * w.w;
            }
            *reinterpret_cast<float4*>(&sh_part[(c32 * 2 + 0) * 100 + 4 * g25]) = a0;
            *reinterpret_cast<float4*>(&sh_part[(c32 * 2 + 1) * 100 + 4 * g25]) = a1;
        }
        __syncthreads();
        if (tid < 200) {
            float s = bo1[rj];
#pragma unroll
            for (int cc = 0; cc < 32; cc++) s += sh_part[(cc * 2 + rrow) * 100 + rj];
            sh_t1[rrow][rj] = fast_tanh(s);
        }
        __syncthreads();

        // ---- Phase A2: h_ode = h + dt * (a @ Wo2 + bo2); scalar, 1024 thr ----
        {
            float acc = bo2[colA];
            const float* wp = Wo2 + colA;
#pragma unroll 10
            for (int j = 0; j < 100; j++) {
                acc += sh_t1[rowA][j] * (*wp); wp += NH;
            }
            sh_ho[rowA][colA] = sh_h[rowA][colA] + dt * acc;
        }
        __syncthreads();

        // ---- Phase B1: tu/tr = tanh(xp + [ho,hs] @ W{u,r}1); gate-split ----
        if (tid < 800) {
            float4 a0 = {0.f,0.f,0.f,0.f}, a1 = {0.f,0.f,0.f,0.f};
            const int kk0 = cB * 64;
            const float* wp = (gateB ? Wr1 : Wu1) + kk0 * 100 + 4 * gB;
            const float *sp0, *sp1;
            if (cB < 8) { sp0 = &sh_ho[0][kk0];      sp1 = &sh_ho[1][kk0]; }
            else        { sp0 = &sh_hs[0][kk0 - NH]; sp1 = &sh_hs[1][kk0 - NH]; }
#pragma unroll 8
            for (int kc = 0; kc < 64; kc++) {
                float4 w = *reinterpret_cast<const float4*>(wp); wp += 100;
                float v0 = sp0[kc], v1 = sp1[kc];
                a0.x += v0 * w.x; a0.y += v0 * w.y; a0.z += v0 * w.z; a0.w += v0 * w.w;
                a1.x += v1 * w.x; a1.y += v1 * w.y; a1.z += v1 * w.z; a1.w += v1 * w.w;
            }
            *reinterpret_cast<float4*>(&sh_part[(cB * 4 + gateB * 2 + 0) * 100 + 4 * gB]) = a0;
            *reinterpret_cast<float4*>(&sh_part[(cB * 4 + gateB * 2 + 1) * 100 + 4 * gB]) = a1;
        }
        __syncthreads();
        if (tid < 400) {
            int idx = (t * NB + b0 + rrow) * 100 + rj;
            if (rgate == 0) {
                float su = g_xpu[idx];
#pragma unroll
                for (int cc = 0; cc < 16; cc++) su += sh_part[(cc * 4 + rrow) * 100 + rj];
                sh_t1[rrow][rj] = fast_tanh(su);
            } else {
                float sr = g_xpr[idx];
#pragma unroll
                for (int cc = 0; cc < 16; cc++) sr += sh_part[(cc * 4 + 2 + rrow) * 100 + rj];
                sh_t2[rrow][rj] = fast_tanh(sr);
            }
        }
        __syncthreads();

        // ---- Phase B2: u/r = sigm(t @ W2 + b2); gate-split halves ----
        if (half == 0) {
            float2 acc = *reinterpret_cast<const float2*>(bu2 + k2);
            const float* wp = Wu2 + k2;
#pragma unroll 10
            for (int j = 0; j < 100; j++) {
                float2 w = *reinterpret_cast<const float2*>(wp); wp += NH;
                float v = sh_t1[row2][j];
                acc.x += v * w.x; acc.y += v * w.y;
            }
            float2 u; u.x = sigm(acc.x); u.y = sigm(acc.y);
            *reinterpret_cast<float2*>(&sh_u[row2][k2]) = u;
        } else {
            float2 acc = *reinterpret_cast<const float2*>(br2 + k2);
            const float* wp = Wr2 + k2;
#pragma unroll 10
            for (int j = 0; j < 100; j++) {
                float2 w = *reinterpret_cast<const float2*>(wp); wp += NH;
                float v = sh_t2[row2][j];
                acc.x += v * w.x; acc.y += v * w.y;
            }
            float2 r; r.x = sigm(acc.x); r.y = sigm(acc.y);
            float2 ho = *reinterpret_cast<float2*>(&sh_ho[row2][k2]);
            float2 hs = *reinterpret_cast<float2*>(&sh_hs[row2][k2]);
            float2 ch, cs;
            ch.x = ho.x * r.x; ch.y = ho.y * r.y;
            cs.x = hs.x * r.x; cs.y = hs.y * r.y;
            *reinterpret_cast<float2*>(&sh_ch[row2][k2]) = ch;
            *reinterpret_cast<float2*>(&sh_cs[row2][k2]) = cs;
        }
        __syncthreads();

        // ---- Phase C1: tn = tanh(xpn + [ch,cs] @ Wn1); 32 chunks of 32 ----
        if (tid < 800) {
            float4 a0 = {0.f,0.f,0.f,0.f}, a1 = {0.f,0.f,0.f,0.f};
            const int kk0 = c32 * 32;
            const float* wp = Wn1 + kk0 * 100 + 4 * g25;
            const float *sp0, *sp1;
            if (kk0 < NH) { sp0 = &sh_ch[0][kk0];      sp1 = &sh_ch[1][kk0]; }
            else          { sp0 = &sh_cs[0][kk0 - NH]; sp1 = &sh_cs[1][kk0 - NH]; }
#pragma unroll 8
            for (int kc = 0; kc < 32; kc++) {
                float4 w = *reinterpret_cast<const float4*>(wp); wp += 100;
                float v0 = sp0[kc], v1 = sp1[kc];
                a0.x += v0 * w.x; a0.y += v0 * w.y; a0.z += v0 * w.z; a0.w += v0 * w.w;
                a1.x += v1 * w.x; a1.y += v1 * w.y; a1.z += v1 * w.z; a1.w += v1 * w.w;
            }
            *reinterpret_cast<float4*>(&sh_part[(c32 * 2 + 0) * 100 + 4 * g25]) = a0;
            *reinterpret_cast<float4*>(&sh_part[(c32 * 2 + 1) * 100 + 4 * g25]) = a1;
        }
        __syncthreads();
        if (tid < 200) {
            int idx = (t * NB + b0 + rrow) * 100 + rj;
            float sn = g_xpn[idx];
#pragma unroll
            for (int cc = 0; cc < 32; cc++) sn += sh_part[(cc * 2 + rrow) * 100 + rj];
            sh_t1[rrow][rj] = fast_tanh(sn);
        }
        __syncthreads();

        // ---- Phase C2: ns = tn @ Wn2 + bn2; m/s halves; state update ----
        if (half == 0) {
            float2 am = *reinterpret_cast<const float2*>(bn2 + k2);
            const float* wp = Wn2 + k2;
#pragma unroll 10
            for (int j = 0; j < 100; j++) {
                float2 w = *reinterpret_cast<const float2*>(wp); wp += 2 * NH;
                float v = sh_t1[row2][j];
                am.x += v * w.x; am.y += v * w.y;
            }
            float2 u  = *reinterpret_cast<float2*>(&sh_u [row2][k2]);
            float2 ho = *reinterpret_cast<float2*>(&sh_ho[row2][k2]);
            float2 hn;
            hn.x = (1.f - u.x) * am.x + u.x * ho.x;
            hn.y = (1.f - u.y) * am.y + u.y * ho.y;
            *reinterpret_cast<float2*>(&sh_h[row2][k2]) = hn;
        } else {
            float2 as = *reinterpret_cast<const float2*>(bn2 + NH + k2);
            const float* wp = Wn2 + NH + k2;
#pragma unroll 10
            for (int j = 0; j < 100; j++) {
                float2 w = *reinterpret_cast<const float2*>(wp); wp += 2 * NH;
                float v = sh_t1[row2][j];
                as.x += v * w.x; as.y += v * w.y;
            }
            float2 u  = *reinterpret_cast<float2*>(&sh_u [row2][k2]);
            float2 hs = *reinterpret_cast<float2*>(&sh_hs[row2][k2]);
            float2 sn;
            sn.x = (1.f - u.x) * fabsf(as.x) + u.x * hs.x;
            sn.y = (1.f - u.y) * fabsf(as.y) + u.y * hs.y;
            *reinterpret_cast<float2*>(&sh_hs[row2][k2]) = sn;
        }
        __syncthreads();
    }

    // ================= Final head =================
    // z1 = tanh([h, hs] @ Wt1 + bt1); 32 chunks of 32
    if (tid < 800) {
        float4 a0 = {0.f,0.f,0.f,0.f}, a1 = {0.f,0.f,0.f,0.f};
        const int kk0 = c32 * 32;
        const float* wp = Wt1 + kk0 * 100 + 4 * g25;
        const float *sp0, *sp1;
        if (kk0 < NH) { sp0 = &sh_h[0][kk0];       sp1 = &sh_h[1][kk0]; }
        else          { sp0 = &sh_hs[0][kk0 - NH]; sp1 = &sh_hs[1][kk0 - NH]; }
#pragma unroll 8
        for (int kc = 0; kc < 32; kc++) {
            float4 w = *reinterpret_cast<const float4*>(wp); wp += 100;
            float v0 = sp0[kc], v1 = sp1[kc];
            a0.x += v0 * w.x; a0.y += v0 * w.y; a0.z += v0 * w.z; a0.w += v0 * w.w;
            a1.x += v1 * w.x; a1.y += v1 * w.y; a1.z += v1 * w.z; a1.w += v1 * w.w;
        }
        *reinterpret_cast<float4*>(&sh_part[(c32 * 2 + 0) * 100 + 4 * g25]) = a0;
        *reinterpret_cast<float4*>(&sh_part[(c32 * 2 + 1) * 100 + 4 * g25]) = a1;
    }
    __syncthreads();
    if (tid < 200) {
        float s = bt1[rj];
#pragma unroll
        for (int cc = 0; cc < 32; cc++) s += sh_part[(cc * 2 + rrow) * 100 + rj];
        sh_t1[rrow][rj] = tanhf(s);   // full-precision tanh for the head
    }
    __syncthreads();
    // z2 = tanh(z1 @ Wt2 + bt2)
    if (tid < 200) {
        float s = bt2[rj];
#pragma unroll 4
        for (int jj = 0; jj < 100; jj++) s += sh_t1[rrow][jj] * Wt2[jj * 100 + rj];
        sh_t2[rrow][rj] = tanhf(s);
    }
    __syncthreads();
    // z3 = z2 @ Wt3 + bt3; mu / sigma halves
    {
        float2 acc = *reinterpret_cast<const float2*>(bt3 + half * NH + k2);
        const float* wp = Wt3 + half * NH + k2;
#pragma unroll 10
        for (int j = 0; j < 100; j++) {
            float2 w = *reinterpret_cast<const float2*>(wp); wp += 2 * NH;
            float z = sh_t2[row2][j];
            acc.x += z * w.x; acc.y += z * w.y;
        }
        int rowg = b0 + row2;
        if (half == 0) {
            *reinterpret_cast<float2*>(out + (size_t)rowg * NH + k2) = acc;
        } else {
            float2 sg; sg.x = fabsf(acc.x); sg.y = fabsf(acc.y);
            *reinterpret_cast<float2*>(out + (size_t)NB * NH + (size_t)rowg * NH + k2) = sg;
        }
    }
}

// ---------------------------------------------------------------------------
extern "C" void kernel_launch(void* const* d_in, const int* in_sizes, int n_in,
                              void* d_out, int out_size) {
    const float* x   = (const float*)d_in[0];
    const float* xt  = (const float*)d_in[1];
    const float* Wu1 = (const float*)d_in[2];
    const float* bu1 = (const float*)d_in[3];
    const float* Wu2 = (const float*)d_in[4];
    const float* bu2 = (const float*)d_in[5];
    const float* Wr1 = (const float*)d_in[6];
    const float* br1 = (const float*)d_in[7];
    const float* Wr2 = (const float*)d_in[8];
    const float* br2 = (const float*)d_in[9];
    const float* Wn1 = (const float*)d_in[10];
    const float* bn1 = (const float*)d_in[11];
    const float* Wn2 = (const float*)d_in[12];
    const float* bn2 = (const float*)d_in[13];
    const float* Wo1 = (const float*)d_in[14];
    const float* bo1 = (const float*)d_in[15];
    const float* Wo2 = (const float*)d_in[16];
    const float* bo2 = (const float*)d_in[17];
    const float* Wt1 = (const float*)d_in[18];
    const float* bt1 = (const float*)d_in[19];
    const float* Wt2 = (const float*)d_in[20];
    const float* bt2 = (const float*)d_in[21];
    const float* Wt3 = (const float*)d_in[22];
    const float* bt3 = (const float*)d_in[23];
    float* out = (float*)d_out;

    dim3 pgrid(NT, 16);
    prep_xproj_kernel<<<pgrid, 256>>>(x, Wu1, bu1, Wr1, br1, Wn1, bn1);
    odegru_kernel<<<NB / 2, NTH>>>(xt,
        Wu1, Wu2, bu2, Wr1, Wr2, br2, Wn1, Wn2, bn2,
        Wo1, bo1, Wo2, bo2, Wt1, bt1, Wt2, bt2, Wt3, bt3, out);
}

// round 9
// speedup vs baseline: 2.6225x; 1.0508x over previous
#include <cuda_runtime.h>
#include <math.h>

// Problem constants: B=256, T=200, X=128, H=512, NU=100, cin=1152.
#define NB 256
#define NT 200
#define NX 128
#define NH 512
#define NTH 1024

// Device-global scratch (allocation-free): x-projections with bias folded.
// Layout [t][b][j], j in [0,100).
__device__ float g_xpu[NT * NB * 100];
__device__ float g_xpr[NT * NB * 100];
__device__ float g_xpn[NT * NB * 100];

// ---------------------------------------------------------------------------
// Prep: g_xp*[t][b][j] = b*1[j] + sum_i x[b][t][i] * W*1[(1024+i)*100 + j]
// ---------------------------------------------------------------------------
__global__ __launch_bounds__(256) void prep_xproj_kernel(
    const float* __restrict__ x,
    const float* __restrict__ Wu1, const float* __restrict__ bu1,
    const float* __restrict__ Wr1, const float* __restrict__ br1,
    const float* __restrict__ Wn1, const float* __restrict__ bn1)
{
    int t   = blockIdx.x;          // 0..199
    int bt  = blockIdx.y;          // 0..15
    int tid = threadIdx.x;
    if (tid >= 200) return;
    int j  = tid % 100;
    int s  = tid / 100;            // 0 or 1
    int b0 = bt * 16 + s * 8;

    float au[8], ar[8], an[8];
    float vbu = bu1[j], vbr = br1[j], vbn = bn1[j];
#pragma unroll
    for (int bi = 0; bi < 8; bi++) { au[bi] = vbu; ar[bi] = vbr; an[bi] = vbn; }

    for (int i = 0; i < NX; i += 4) {
        float wu[4], wr[4], wn[4];
#pragma unroll
        for (int c = 0; c < 4; c++) {
            int wi = (2 * NH + i + c) * 100 + j;
            wu[c] = __ldg(Wu1 + wi);
            wr[c] = __ldg(Wr1 + wi);
            wn[c] = __ldg(Wn1 + wi);
        }
#pragma unroll
        for (int bi = 0; bi < 8; bi++) {
            float4 xv = *reinterpret_cast<const float4*>(
                x + ((size_t)(b0 + bi) * NT + t) * NX + i);
            au[bi] += xv.x * wu[0] + xv.y * wu[1] + xv.z * wu[2] + xv.w * wu[3];
            ar[bi] += xv.x * wr[0] + xv.y * wr[1] + xv.z * wr[2] + xv.w * wr[3];
            an[bi] += xv.x * wn[0] + xv.y * wn[1] + xv.z * wn[2] + xv.w * wn[3];
        }
    }
#pragma unroll
    for (int bi = 0; bi < 8; bi++) {
        int idx = (t * NB + b0 + bi) * 100 + j;
        g_xpu[idx] = au[bi];
        g_xpr[idx] = ar[bi];
        g_xpn[idx] = an[bi];
    }
}

__device__ __forceinline__ float fast_tanh(float x) {
    float y;
    asm("tanh.approx.f32 %0, %1;" : "=f"(y) : "f"(x));
    return y;
}
__device__ __forceinline__ float sigm(float v) {
    return 0.5f * fast_tanh(0.5f * v) + 0.5f;
}

// ---------------------------------------------------------------------------
// Persistent recurrent kernel: 128 blocks x 1024 threads (32 warps/SM).
// Block bx owns batch rows 2bx, 2bx+1 for all 200 steps + final head.
// Phase-2 GEMMs: one thread per OUTPUT COLUMN, both batch rows per thread,
// so every weight element is loaded exactly once per block per step.
// ---------------------------------------------------------------------------
__global__ __launch_bounds__(NTH) void odegru_kernel(
    const float* __restrict__ xt,
    const float* __restrict__ Wu1, const float* __restrict__ Wu2, const float* __restrict__ bu2,
    const float* __restrict__ Wr1, const float* __restrict__ Wr2, const float* __restrict__ br2,
    const float* __restrict__ Wn1, const float* __restrict__ Wn2, const float* __restrict__ bn2,
    const float* __restrict__ Wo1, const float* __restrict__ bo1,
    const float* __restrict__ Wo2, const float* __restrict__ bo2,
    const float* __restrict__ Wt1, const float* __restrict__ bt1,
    const float* __restrict__ Wt2, const float* __restrict__ bt2,
    const float* __restrict__ Wt3, const float* __restrict__ bt3,
    float* __restrict__ out)
{
    __shared__ __align__(16) float sh_h [2][NH];
    __shared__ __align__(16) float sh_hs[2][NH];
    __shared__ __align__(16) float sh_ho[2][NH];
    __shared__ __align__(16) float sh_u [2][NH];
    __shared__ __align__(16) float sh_ch[2][NH];
    __shared__ __align__(16) float sh_cs[2][NH];
    __shared__ __align__(16) float sh_t1[2][100];
    __shared__ __align__(16) float sh_t2[2][100];
    // Phase-1 partials. Viewed as [32][2][100] (A1/C1/head) or [16][4][100] (B1).
    __shared__ __align__(16) float sh_part[32 * 2 * 100];
    __shared__ float sh_dt[NT];

    const int tid = threadIdx.x;
    const int b0  = blockIdx.x * 2;

    // split-k mapping for 800-thread phase-1 GEMMs
    const int g25 = tid % 25;           // j-group: cols 4g..4g+3
    const int c32 = tid / 25;           // chunk 0..31 (tid<800)
    // B1 mapping (tid<800): gate, then 16 chunks x 25 groups
    const int gateB = tid / 400;        // 0=u, 1=r
    const int sB    = tid % 400;
    const int cB    = sB / 25;          // 0..15
    const int gB    = sB % 25;
    // reduce mappings
    const int rrow  = (tid / 100) & 1, rj = tid % 100;  // tid<200 / tid<400
    const int rgate = tid / 200;                         // tid<400
    // phase-2 column mappings (one output column, both rows)
    const int gcol  = tid >> 9;          // B2: 0=u-gate, 1=r-gate; C2: 0=m, 1=s
    const int col   = tid & 511;         // column within gate/half

    // init: dt table + zero states
    if (tid < NT) {
        float v;
        if (tid == 0)      v = -0.01f;
        else if (tid == 1) v = xt[NT - 1] - xt[0];
        else               v = xt[tid - 2] - xt[tid - 1];
        sh_dt[tid] = v;
    }
    for (int k = tid; k < NH; k += NTH) {
        sh_h[0][k] = 0.f; sh_h[1][k] = 0.f;
        sh_hs[0][k] = 0.f; sh_hs[1][k] = 0.f;
    }
    __syncthreads();

    for (int t = 0; t < NT; t++) {
        const float dt = sh_dt[t];

        // Prefetch this step's x-projection values (hides L2/DRAM latency
        // behind phases A1..B1 instead of exposing it inside the reduces).
        float pf_ur = 0.f, pf_n = 0.f;
        if (tid < 400) {
            int idx = (t * NB + b0 + rrow) * 100 + rj;
            pf_ur = rgate ? __ldg(g_xpr + idx) : __ldg(g_xpu + idx);
            if (tid < 200) pf_n = __ldg(g_xpn + idx);
        }

        // ---- Phase A1: a = tanh(h @ Wo1 + bo1); 32 chunks of 16 rows ----
        if (tid < 800) {
            float4 a0 = {0.f,0.f,0.f,0.f}, a1 = {0.f,0.f,0.f,0.f};
            const int kk0 = c32 * 16;
            const float* wp = Wo1 + kk0 * 100 + 4 * g25;
            const float* s0 = &sh_h[0][kk0];
            const float* s1 = &sh_h[1][kk0];
#pragma unroll
            for (int kc = 0; kc < 16; kc++) {
                float4 w = *reinterpret_cast<const float4*>(wp); wp += 100;
                float v0 = s0[kc], v1 = s1[kc];
                a0.x += v0 * w.x; a0.y += v0 * w.y; a0.z += v0 * w.z; a0.w += v0 * w.w;
                a1.x += v1 * w.x; a1.y += v1 * w.y; a1.z += v1 * w.z; a1.w += v1 * w.w;
            }
            *reinterpret_cast<float4*>(&sh_part[(c32 * 2 + 0) * 100 + 4 * g25]) = a0;
            *reinterpret_cast<float4*>(&sh_part[(c32 * 2 + 1) * 100 + 4 * g25]) = a1;
        }
        __syncthreads();
        if (tid < 200) {
            float s = bo1[rj];
#pragma unroll
            for (int cc = 0; cc < 32; cc++) s += sh_part[(cc * 2 + rrow) * 100 + rj];
            sh_t1[rrow][rj] = fast_tanh(s);
        }
        __syncthreads();

        // ---- Phase A2: h_ode = h + dt*(a @ Wo2 + bo2); 512 cols, both rows ----
        if (tid < 512) {
            float b = bo2[col];
            float a0 = b, a1 = b;
            const float* wp = Wo2 + col;
#pragma unroll 10
            for (int j = 0; j < 100; j++) {
                float w = *wp; wp += NH;
                a0 += sh_t1[0][j] * w;
                a1 += sh_t1[1][j] * w;
            }
            sh_ho[0][col] = sh_h[0][col] + dt * a0;
            sh_ho[1][col] = sh_h[1][col] + dt * a1;
        }
        __syncthreads();

        // ---- Phase B1: tu/tr = tanh(xp + [ho,hs] @ W{u,r}1); gate-split ----
        if (tid < 800) {
            float4 a0 = {0.f,0.f,0.f,0.f}, a1 = {0.f,0.f,0.f,0.f};
            const int kk0 = cB * 64;
            const float* wp = (gateB ? Wr1 : Wu1) + kk0 * 100 + 4 * gB;
            const float *sp0, *sp1;
            if (cB < 8) { sp0 = &sh_ho[0][kk0];      sp1 = &sh_ho[1][kk0]; }
            else        { sp0 = &sh_hs[0][kk0 - NH]; sp1 = &sh_hs[1][kk0 - NH]; }
#pragma unroll 8
            for (int kc = 0; kc < 64; kc++) {
                float4 w = *reinterpret_cast<const float4*>(wp); wp += 100;
                float v0 = sp0[kc], v1 = sp1[kc];
                a0.x += v0 * w.x; a0.y += v0 * w.y; a0.z += v0 * w.z; a0.w += v0 * w.w;
                a1.x += v1 * w.x; a1.y += v1 * w.y; a1.z += v1 * w.z; a1.w += v1 * w.w;
            }
            *reinterpret_cast<float4*>(&sh_part[(cB * 4 + gateB * 2 + 0) * 100 + 4 * gB]) = a0;
            *reinterpret_cast<float4*>(&sh_part[(cB * 4 + gateB * 2 + 1) * 100 + 4 * gB]) = a1;
        }
        __syncthreads();
        if (tid < 400) {
            if (rgate == 0) {
                float su = pf_ur;
#pragma unroll
                for (int cc = 0; cc < 16; cc++) su += sh_part[(cc * 4 + rrow) * 100 + rj];
                sh_t1[rrow][rj] = fast_tanh(su);
            } else {
                float sr = pf_ur;
#pragma unroll
                for (int cc = 0; cc < 16; cc++) sr += sh_part[(cc * 4 + 2 + rrow) * 100 + rj];
                sh_t2[rrow][rj] = fast_tanh(sr);
            }
        }
        __syncthreads();

        // ---- Phase B2: u/r per column, both rows; weights loaded once ----
        if (gcol == 0) {
            float b = bu2[col];
            float a0 = b, a1 = b;
            const float* wp = Wu2 + col;
#pragma unroll 10
            for (int j = 0; j < 100; j++) {
                float w = *wp; wp += NH;
                a0 += sh_t1[0][j] * w;
                a1 += sh_t1[1][j] * w;
            }
            sh_u[0][col] = sigm(a0);
            sh_u[1][col] = sigm(a1);
        } else {
            float b = br2[col];
            float a0 = b, a1 = b;
            const float* wp = Wr2 + col;
#pragma unroll 10
            for (int j = 0; j < 100; j++) {
                float w = *wp; wp += NH;
                a0 += sh_t2[0][j] * w;
                a1 += sh_t2[1][j] * w;
            }
            float r0 = sigm(a0), r1 = sigm(a1);
            sh_ch[0][col] = sh_ho[0][col] * r0;
            sh_ch[1][col] = sh_ho[1][col] * r1;
            sh_cs[0][col] = sh_hs[0][col] * r0;
            sh_cs[1][col] = sh_hs[1][col] * r1;
        }
        __syncthreads();

        // ---- Phase C1: tn = tanh(xpn + [ch,cs] @ Wn1); 32 chunks of 32 ----
        if (tid < 800) {
            float4 a0 = {0.f,0.f,0.f,0.f}, a1 = {0.f,0.f,0.f,0.f};
            const int kk0 = c32 * 32;
            const float* wp = Wn1 + kk0 * 100 + 4 * g25;
            const float *sp0, *sp1;
            if (kk0 < NH) { sp0 = &sh_ch[0][kk0];      sp1 = &sh_ch[1][kk0]; }
            else          { sp0 = &sh_cs[0][kk0 - NH]; sp1 = &sh_cs[1][kk0 - NH]; }
#pragma unroll 8
            for (int kc = 0; kc < 32; kc++) {
                float4 w = *reinterpret_cast<const float4*>(wp); wp += 100;
                float v0 = sp0[kc], v1 = sp1[kc];
                a0.x += v0 * w.x; a0.y += v0 * w.y; a0.z += v0 * w.z; a0.w += v0 * w.w;
                a1.x += v1 * w.x; a1.y += v1 * w.y; a1.z += v1 * w.z; a1.w += v1 * w.w;
            }
            *reinterpret_cast<float4*>(&sh_part[(c32 * 2 + 0) * 100 + 4 * g25]) = a0;
            *reinterpret_cast<float4*>(&sh_part[(c32 * 2 + 1) * 100 + 4 * g25]) = a1;
        }
        __syncthreads();
        if (tid < 200) {
            float sn = pf_n;
#pragma unroll
            for (int cc = 0; cc < 32; cc++) sn += sh_part[(cc * 2 + rrow) * 100 + rj];
            sh_t1[rrow][rj] = fast_tanh(sn);
        }
        __syncthreads();

        // ---- Phase C2: ns = tn @ Wn2 + bn2; m/s per column, both rows ----
        if (gcol == 0) {
            float b = bn2[col];
            float a0 = b, a1 = b;
            const float* wp = Wn2 + col;
#pragma unroll 10
            for (int j = 0; j < 100; j++) {
                float w = *wp; wp += 2 * NH;
                a0 += sh_t1[0][j] * w;
                a1 += sh_t1[1][j] * w;
            }
            float u0 = sh_u[0][col], u1 = sh_u[1][col];
            sh_h[0][col] = (1.f - u0) * a0 + u0 * sh_ho[0][col];
            sh_h[1][col] = (1.f - u1) * a1 + u1 * sh_ho[1][col];
        } else {
            float b = bn2[NH + col];
            float a0 = b, a1 = b;
            const float* wp = Wn2 + NH + col;
#pragma unroll 10
            for (int j = 0; j < 100; j++) {
                float w = *wp; wp += 2 * NH;
                a0 += sh_t1[0][j] * w;
                a1 += sh_t1[1][j] * w;
            }
            float u0 = sh_u[0][col], u1 = sh_u[1][col];
            sh_hs[0][col] = (1.f - u0) * fabsf(a0) + u0 * sh_hs[0][col];
            sh_hs[1][col] = (1.f - u1) * fabsf(a1) + u1 * sh_hs[1][col];
        }
        __syncthreads();
    }

    // ================= Final head =================
    // z1 = tanh([h, hs] @ Wt1 + bt1); 32 chunks of 32
    if (tid < 800) {
        float4 a0 = {0.f,0.f,0.f,0.f}, a1 = {0.f,0.f,0.f,0.f};
        const int kk0 = c32 * 32;
        const float* wp = Wt1 + kk0 * 100 + 4 * g25;
        const float *sp0, *sp1;
        if (kk0 < NH) { sp0 = &sh_h[0][kk0];       sp1 = &sh_h[1][kk0]; }
        else          { sp0 = &sh_hs[0][kk0 - NH]; sp1 = &sh_hs[1][kk0 - NH]; }
#pragma unroll 8
        for (int kc = 0; kc < 32; kc++) {
            float4 w = *reinterpret_cast<const float4*>(wp); wp += 100;
            float v0 = sp0[kc], v1 = sp1[kc];
            a0.x += v0 * w.x; a0.y += v0 * w.y; a0.z += v0 * w.z; a0.w += v0 * w.w;
            a1.x += v1 * w.x; a1.y += v1 * w.y; a1.z += v1 * w.z; a1.w += v1 * w.w;
        }
        *reinterpret_cast<float4*>(&sh_part[(c32 * 2 + 0) * 100 + 4 * g25]) = a0;
        *reinterpret_cast<float4*>(&sh_part[(c32 * 2 + 1) * 100 + 4 * g25]) = a1;
    }
    __syncthreads();
    if (tid < 200) {
        float s = bt1[rj];
#pragma unroll
        for (int cc = 0; cc < 32; cc++) s += sh_part[(cc * 2 + rrow) * 100 + rj];
        sh_t1[rrow][rj] = tanhf(s);   // full-precision tanh for the head
    }
    __syncthreads();
    // z2 = tanh(z1 @ Wt2 + bt2)
    if (tid < 200) {
        float s = bt2[rj];
#pragma unroll 4
        for (int jj = 0; jj < 100; jj++) s += sh_t1[rrow][jj] * Wt2[jj * 100 + rj];
        sh_t2[rrow][rj] = tanhf(s);
    }
    __syncthreads();
    // z3 = z2 @ Wt3 + bt3; one column per thread, both rows
    {
        float b = bt3[tid];
        float a0 = b, a1 = b;
        const float* wp = Wt3 + tid;
#pragma unroll 10
        for (int j = 0; j < 100; j++) {
            float w = *wp; wp += 2 * NH;
            a0 += sh_t2[0][j] * w;
            a1 += sh_t2[1][j] * w;
        }
        if (gcol == 0) {   // mu columns
            out[(size_t)(b0 + 0) * NH + col] = a0;
            out[(size_t)(b0 + 1) * NH + col] = a1;
        } else {           // sigma columns
            out[(size_t)NB * NH + (size_t)(b0 + 0) * NH + col] = fabsf(a0);
            out[(size_t)NB * NH + (size_t)(b0 + 1) * NH + col] = fabsf(a1);
        }
    }
}

// ---------------------------------------------------------------------------
extern "C" void kernel_launch(void* const* d_in, const int* in_sizes, int n_in,
                              void* d_out, int out_size) {
    const float* x   = (const float*)d_in[0];
    const float* xt  = (const float*)d_in[1];
    const float* Wu1 = (const float*)d_in[2];
    const float* bu1 = (const float*)d_in[3];
    const float* Wu2 = (const float*)d_in[4];
    const float* bu2 = (const float*)d_in[5];
    const float* Wr1 = (const float*)d_in[6];
    const float* br1 = (const float*)d_in[7];
    const float* Wr2 = (const float*)d_in[8];
    const float* br2 = (const float*)d_in[9];
    const float* Wn1 = (const float*)d_in[10];
    const float* bn1 = (const float*)d_in[11];
    const float* Wn2 = (const float*)d_in[12];
    const float* bn2 = (const float*)d_in[13];
    const float* Wo1 = (const float*)d_in[14];
    const float* bo1 = (const float*)d_in[15];
    const float* Wo2 = (const float*)d_in[16];
    const float* bo2 = (const float*)d_in[17];
    const float* Wt1 = (const float*)d_in[18];
    const float* bt1 = (const float*)d_in[19];
    const float* Wt2 = (const float*)d_in[20];
    const float* bt2 = (const float*)d_in[21];
    const float* Wt3 = (const float*)d_in[22];
    const float* bt3 = (const float*)d_in[23];
    float* out = (float*)d_out;

    dim3 pgrid(NT, 16);
    prep_xproj_kernel<<<pgrid, 256>>>(x, Wu1, bu1, Wr1, br1, Wn1, bn1);
    odegru_kernel<<<NB / 2, NTH>>>(xt,
        Wu1, Wu2, bu2, Wr1, Wr2, br2, Wn1, Wn2, bn2,
        Wo1, bo1, Wo2, bo2, Wt1, bt1, Wt2, bt2, Wt3, bt3, out);
}

// round 10
// speedup vs baseline: 2.9777x; 1.1355x over previous
#include <cuda_runtime.h>
#include <cuda_fp16.h>
#include <math.h>

// Problem constants: B=256, T=200, X=128, H=512, NU=100, cin=1152.
#define NB 256
#define NT 200
#define NX 128
#define NH 512
#define NTH 1024

// Device-global scratch (allocation-free).
__device__ float g_xpu[NT * NB * 100];
__device__ float g_xpr[NT * NB * 100];
__device__ float g_xpn[NT * NB * 100];

// fp16 weight streams (packed layouts; see pack kernels).
__device__ __half g_hWo1[512  * 100];   // phase-1 pack: [k2][g][8]
__device__ __half g_hWu1[1024 * 100];
__device__ __half g_hWr1[1024 * 100];
__device__ __half g_hWn1[1024 * 100];
__device__ __half g_hWo2[100 * 512];    // phase-2 pack: [j2][col]{2}
__device__ __half g_hWu2[100 * 512];
__device__ __half g_hWr2[100 * 512];
__device__ __half g_hWn2[100 * 1024];

// ---------------------------------------------------------------------------
// Pack phase-1 weights: src [nrows][100] fp32 ->
//   dst[(k/2 * 25 + j/4)*8 + (k&1)*4 + (j%4)] = fp16(src[k*100+j])
// ---------------------------------------------------------------------------
__global__ void pack_p1_kernel(const float* __restrict__ src, __half* __restrict__ dst, int nrows) {
    int n = nrows * 100;
    for (int i = blockIdx.x * blockDim.x + threadIdx.x; i < n; i += gridDim.x * blockDim.x) {
        int k = i / 100, j = i % 100;
        dst[((k >> 1) * 25 + (j >> 2)) * 8 + (k & 1) * 4 + (j & 3)] = __float2half_rn(src[i]);
    }
}

// ---------------------------------------------------------------------------
// Pack phase-2 weights: src [100][ncol] fp32 ->
//   dst[((j/2)*ncol + c)*2 + (j&1)] = fp16(src[j*ncol+c])   (half2 per (j-pair,col))
// ---------------------------------------------------------------------------
__global__ void pack_p2_kernel(const float* __restrict__ src, __half* __restrict__ dst, int ncol) {
    int n = 100 * ncol;
    for (int i = blockIdx.x * blockDim.x + threadIdx.x; i < n; i += gridDim.x * blockDim.x) {
        int j = i / ncol, c = i % ncol;
        dst[(((j >> 1) * ncol) + c) * 2 + (j & 1)] = __float2half_rn(src[i]);
    }
}

// ---------------------------------------------------------------------------
// Prep: g_xp*[t][b][j] = b*1[j] + sum_i x[b][t][i] * W*1[(1024+i)*100 + j]  (fp32)
// ---------------------------------------------------------------------------
__global__ __launch_bounds__(256) void prep_xproj_kernel(
    const float* __restrict__ x,
    const float* __restrict__ Wu1, const float* __restrict__ bu1,
    const float* __restrict__ Wr1, const float* __restrict__ br1,
    const float* __restrict__ Wn1, const float* __restrict__ bn1)
{
    int t   = blockIdx.x;
    int bt  = blockIdx.y;
    int tid = threadIdx.x;
    if (tid >= 200) return;
    int j  = tid % 100;
    int s  = tid / 100;
    int b0 = bt * 16 + s * 8;

    float au[8], ar[8], an[8];
    float vbu = bu1[j], vbr = br1[j], vbn = bn1[j];
#pragma unroll
    for (int bi = 0; bi < 8; bi++) { au[bi] = vbu; ar[bi] = vbr; an[bi] = vbn; }

    for (int i = 0; i < NX; i += 4) {
        float wu[4], wr[4], wn[4];
#pragma unroll
        for (int c = 0; c < 4; c++) {
            int wi = (2 * NH + i + c) * 100 + j;
            wu[c] = __ldg(Wu1 + wi);
            wr[c] = __ldg(Wr1 + wi);
            wn[c] = __ldg(Wn1 + wi);
        }
#pragma unroll
        for (int bi = 0; bi < 8; bi++) {
            float4 xv = *reinterpret_cast<const float4*>(
                x + ((size_t)(b0 + bi) * NT + t) * NX + i);
            au[bi] += xv.x * wu[0] + xv.y * wu[1] + xv.z * wu[2] + xv.w * wu[3];
            ar[bi] += xv.x * wr[0] + xv.y * wr[1] + xv.z * wr[2] + xv.w * wr[3];
            an[bi] += xv.x * wn[0] + xv.y * wn[1] + xv.z * wn[2] + xv.w * wn[3];
        }
    }
#pragma unroll
    for (int bi = 0; bi < 8; bi++) {
        int idx = (t * NB + b0 + bi) * 100 + j;
        g_xpu[idx] = au[bi];
        g_xpr[idx] = ar[bi];
        g_xpn[idx] = an[bi];
    }
}

__device__ __forceinline__ float fast_tanh(float x) {
    float y;
    asm("tanh.approx.f32 %0, %1;" : "=f"(y) : "f"(x));
    return y;
}
__device__ __forceinline__ float sigm(float v) {
    return 0.5f * fast_tanh(0.5f * v) + 0.5f;
}

// Phase-1 fp16 MAC helper: one uint4 = 8 halves = rows (2k2,2k2+1) x cols (4g..4g+3)
#define P1_STEP(qptr, va, vb, ua, ub, acc0, acc1) do {                     \
    uint4 q = *reinterpret_cast<const uint4*>(qptr);                        \
    const __half2* hh = reinterpret_cast<const __half2*>(&q);               \
    float2 wa01 = __half22float2(hh[0]);                                    \
    float2 wa23 = __half22float2(hh[1]);                                    \
    float2 wb01 = __half22float2(hh[2]);                                    \
    float2 wb23 = __half22float2(hh[3]);                                    \
    acc0.x += va * wa01.x + vb * wb01.x;                                    \
    acc0.y += va * wa01.y + vb * wb01.y;                                    \
    acc0.z += va * wa23.x + vb * wb23.x;                                    \
    acc0.w += va * wa23.y + vb * wb23.y;                                    \
    acc1.x += ua * wa01.x + ub * wb01.x;                                    \
    acc1.y += ua * wa01.y + ub * wb01.y;                                    \
    acc1.z += ua * wa23.x + ub * wb23.x;                                    \
    acc1.w += ua * wa23.y + ub * wb23.y;                                    \
} while (0)

// ---------------------------------------------------------------------------
// Persistent recurrent kernel: 128 blocks x 1024 threads (32 warps/SM).
// fp16 weight streams, fp32 accumulate. Phase-2: one thread per output
// column, both batch rows -> every weight loaded once per block per step.
// ---------------------------------------------------------------------------
__global__ __launch_bounds__(NTH) void odegru_kernel(
    const float* __restrict__ xt,
    const float* __restrict__ Wt1, const float* __restrict__ bt1,
    const float* __restrict__ Wt2, const float* __restrict__ bt2,
    const float* __restrict__ Wt3, const float* __restrict__ bt3,
    const float* __restrict__ bo1, const float* __restrict__ bo2,
    const float* __restrict__ bu2, const float* __restrict__ br2,
    const float* __restrict__ bn2,
    float* __restrict__ out)
{
    __shared__ __align__(16) float sh_h [2][NH];
    __shared__ __align__(16) float sh_hs[2][NH];
    __shared__ __align__(16) float sh_ho[2][NH];
    __shared__ __align__(16) float sh_u [2][NH];
    __shared__ __align__(16) float sh_ch[2][NH];
    __shared__ __align__(16) float sh_cs[2][NH];
    __shared__ __align__(16) float sh_t1[2][100];
    __shared__ __align__(16) float sh_t2[2][100];
    __shared__ __align__(16) float sh_part[32 * 2 * 100];
    __shared__ float sh_dt[NT];

    const int tid = threadIdx.x;
    const int b0  = blockIdx.x * 2;

    // phase-1 mappings
    const int g25 = tid % 25;           // j-group (4 cols)
    const int c32 = tid / 25;           // chunk 0..31 (tid<800)
    const int gateB = tid / 400;        // B1: 0=u, 1=r
    const int sB    = tid % 400;
    const int cB    = sB / 25;          // 0..15
    const int gB    = sB % 25;
    // reduce mappings
    const int rrow  = (tid / 100) & 1, rj = tid % 100;
    const int rgate = tid / 200;
    // phase-2 column mappings
    const int gcol  = tid >> 9;
    const int col   = tid & 511;

    if (tid < NT) {
        float v;
        if (tid == 0)      v = -0.01f;
        else if (tid == 1) v = xt[NT - 1] - xt[0];
        else               v = xt[tid - 2] - xt[tid - 1];
        sh_dt[tid] = v;
    }
    for (int k = tid; k < NH; k += NTH) {
        sh_h[0][k] = 0.f; sh_h[1][k] = 0.f;
        sh_hs[0][k] = 0.f; sh_hs[1][k] = 0.f;
    }
    __syncthreads();

    for (int t = 0; t < NT; t++) {
        const float dt = sh_dt[t];

        // Prefetch this step's x-projection values.
        float pf_ur = 0.f, pf_n = 0.f;
        if (tid < 400) {
            int idx = (t * NB + b0 + rrow) * 100 + rj;
            pf_ur = rgate ? __ldg(g_xpr + idx) : __ldg(g_xpu + idx);
            if (tid < 200) pf_n = __ldg(g_xpn + idx);
        }

        // ---- Phase A1: a = tanh(h @ Wo1 + bo1); 32 chunks of 16 rows (8 k2) ----
        if (tid < 800) {
            float4 a0 = {0.f,0.f,0.f,0.f}, a1 = {0.f,0.f,0.f,0.f};
            const __half* wp = g_hWo1 + ((size_t)(c32 * 8) * 25 + g25) * 8;
            const float* s0 = &sh_h[0][c32 * 16];
            const float* s1 = &sh_h[1][c32 * 16];
#pragma unroll
            for (int k2 = 0; k2 < 8; k2++) {
                P1_STEP(wp, s0[2*k2], s0[2*k2+1], s1[2*k2], s1[2*k2+1], a0, a1);
                wp += 200;
            }
            *reinterpret_cast<float4*>(&sh_part[(c32 * 2 + 0) * 100 + 4 * g25]) = a0;
            *reinterpret_cast<float4*>(&sh_part[(c32 * 2 + 1) * 100 + 4 * g25]) = a1;
        }
        __syncthreads();
        if (tid < 200) {
            float s = bo1[rj];
#pragma unroll
            for (int cc = 0; cc < 32; cc++) s += sh_part[(cc * 2 + rrow) * 100 + rj];
            sh_t1[rrow][rj] = fast_tanh(s);
        }
        __syncthreads();

        // ---- Phase A2: h_ode = h + dt*(a @ Wo2 + bo2); 512 cols, both rows ----
        if (tid < 512) {
            float b = bo2[col];
            float a0 = b, a1 = b;
            const __half2* wp = reinterpret_cast<const __half2*>(g_hWo2) + col;
#pragma unroll 10
            for (int j2 = 0; j2 < 50; j2++) {
                float2 w = __half22float2(*wp); wp += NH;
                a0 += sh_t1[0][2*j2] * w.x + sh_t1[0][2*j2+1] * w.y;
                a1 += sh_t1[1][2*j2] * w.x + sh_t1[1][2*j2+1] * w.y;
            }
            sh_ho[0][col] = sh_h[0][col] + dt * a0;
            sh_ho[1][col] = sh_h[1][col] + dt * a1;
        }
        __syncthreads();

        // ---- Phase B1: tu/tr = tanh(xp + [ho,hs] @ W{u,r}1); 16 chunks of 64 (32 k2) ----
        if (tid < 800) {
            float4 a0 = {0.f,0.f,0.f,0.f}, a1 = {0.f,0.f,0.f,0.f};
            const int kk0 = cB * 64;
            const __half* wp = (gateB ? g_hWr1 : g_hWu1) + ((size_t)(cB * 32) * 25 + gB) * 8;
            const float *sp0, *sp1;
            if (cB < 8) { sp0 = &sh_ho[0][kk0];      sp1 = &sh_ho[1][kk0]; }
            else        { sp0 = &sh_hs[0][kk0 - NH]; sp1 = &sh_hs[1][kk0 - NH]; }
#pragma unroll 8
            for (int k2 = 0; k2 < 32; k2++) {
                P1_STEP(wp, sp0[2*k2], sp0[2*k2+1], sp1[2*k2], sp1[2*k2+1], a0, a1);
                wp += 200;
            }
            *reinterpret_cast<float4*>(&sh_part[(cB * 4 + gateB * 2 + 0) * 100 + 4 * gB]) = a0;
            *reinterpret_cast<float4*>(&sh_part[(cB * 4 + gateB * 2 + 1) * 100 + 4 * gB]) = a1;
        }
        __syncthreads();
        if (tid < 400) {
            if (rgate == 0) {
                float su = pf_ur;
#pragma unroll
                for (int cc = 0; cc < 16; cc++) su += sh_part[(cc * 4 + rrow) * 100 + rj];
                sh_t1[rrow][rj] = fast_tanh(su);
            } else {
                float sr = pf_ur;
#pragma unroll
                for (int cc = 0; cc < 16; cc++) sr += sh_part[(cc * 4 + 2 + rrow) * 100 + rj];
                sh_t2[rrow][rj] = fast_tanh(sr);
            }
        }
        __syncthreads();

        // ---- Phase B2: u/r per column, both rows ----
        if (gcol == 0) {
            float b = bu2[col];
            float a0 = b, a1 = b;
            const __half2* wp = reinterpret_cast<const __half2*>(g_hWu2) + col;
#pragma unroll 10
            for (int j2 = 0; j2 < 50; j2++) {
                float2 w = __half22float2(*wp); wp += NH;
                a0 += sh_t1[0][2*j2] * w.x + sh_t1[0][2*j2+1] * w.y;
                a1 += sh_t1[1][2*j2] * w.x + sh_t1[1][2*j2+1] * w.y;
            }
            sh_u[0][col] = sigm(a0);
            sh_u[1][col] = sigm(a1);
        } else {
            float b = br2[col];
            float a0 = b, a1 = b;
            const __half2* wp = reinterpret_cast<const __half2*>(g_hWr2) + col;
#pragma unroll 10
            for (int j2 = 0; j2 < 50; j2++) {
                float2 w = __half22float2(*wp); wp += NH;
                a0 += sh_t2[0][2*j2] * w.x + sh_t2[0][2*j2+1] * w.y;
                a1 += sh_t2[1][2*j2] * w.x + sh_t2[1][2*j2+1] * w.y;
            }
            float r0 = sigm(a0), r1 = sigm(a1);
            sh_ch[0][col] = sh_ho[0][col] * r0;
            sh_ch[1][col] = sh_ho[1][col] * r1;
            sh_cs[0][col] = sh_hs[0][col] * r0;
            sh_cs[1][col] = sh_hs[1][col] * r1;
        }
        __syncthreads();

        // ---- Phase C1: tn = tanh(xpn + [ch,cs] @ Wn1); 32 chunks of 32 rows (16 k2) ----
        if (tid < 800) {
            float4 a0 = {0.f,0.f,0.f,0.f}, a1 = {0.f,0.f,0.f,0.f};
            const int kk0 = c32 * 32;
            const __half* wp = g_hWn1 + ((size_t)(c32 * 16) * 25 + g25) * 8;
            const float *sp0, *sp1;
            if (kk0 < NH) { sp0 = &sh_ch[0][kk0];      sp1 = &sh_ch[1][kk0]; }
            else          { sp0 = &sh_cs[0][kk0 - NH]; sp1 = &sh_cs[1][kk0 - NH]; }
#pragma unroll 8
            for (int k2 = 0; k2 < 16; k2++) {
                P1_STEP(wp, sp0[2*k2], sp0[2*k2+1], sp1[2*k2], sp1[2*k2+1], a0, a1);
                wp += 200;
            }
            *reinterpret_cast<float4*>(&sh_part[(c32 * 2 + 0) * 100 + 4 * g25]) = a0;
            *reinterpret_cast<float4*>(&sh_part[(c32 * 2 + 1) * 100 + 4 * g25]) = a1;
        }
        __syncthreads();
        if (tid < 200) {
            float sn = pf_n;
#pragma unroll
            for (int cc = 0; cc < 32; cc++) sn += sh_part[(cc * 2 + rrow) * 100 + rj];
            sh_t1[rrow][rj] = fast_tanh(sn);
        }
        __syncthreads();

        // ---- Phase C2: ns = tn @ Wn2 + bn2; m/s per column, both rows ----
        {
            float b = bn2[gcol * NH + col];
            float a0 = b, a1 = b;
            const __half2* wp = reinterpret_cast<const __half2*>(g_hWn2) + gcol * NH + col;
#pragma unroll 10
            for (int j2 = 0; j2 < 50; j2++) {
                float2 w = __half22float2(*wp); wp += 2 * NH;
                a0 += sh_t1[0][2*j2] * w.x + sh_t1[0][2*j2+1] * w.y;
                a1 += sh_t1[1][2*j2] * w.x + sh_t1[1][2*j2+1] * w.y;
            }
            if (gcol == 0) {
                float u0 = sh_u[0][col], u1 = sh_u[1][col];
                sh_h[0][col] = (1.f - u0) * a0 + u0 * sh_ho[0][col];
                sh_h[1][col] = (1.f - u1) * a1 + u1 * sh_ho[1][col];
            } else {
                float u0 = sh_u[0][col], u1 = sh_u[1][col];
                sh_hs[0][col] = (1.f - u0) * fabsf(a0) + u0 * sh_hs[0][col];
                sh_hs[1][col] = (1.f - u1) * fabsf(a1) + u1 * sh_hs[1][col];
            }
        }
        __syncthreads();
    }

    // ================= Final head (fp32 weights, run once) =================
    if (tid < 800) {
        float4 a0 = {0.f,0.f,0.f,0.f}, a1 = {0.f,0.f,0.f,0.f};
        const int kk0 = c32 * 32;
        const float* wp = Wt1 + kk0 * 100 + 4 * g25;
        const float *sp0, *sp1;
        if (kk0 < NH) { sp0 = &sh_h[0][kk0];       sp1 = &sh_h[1][kk0]; }
        else          { sp0 = &sh_hs[0][kk0 - NH]; sp1 = &sh_hs[1][kk0 - NH]; }
#pragma unroll 8
        for (int kc = 0; kc < 32; kc++) {
            float4 w = *reinterpret_cast<const float4*>(wp); wp += 100;
            float v0 = sp0[kc], v1 = sp1[kc];
            a0.x += v0 * w.x; a0.y += v0 * w.y; a0.z += v0 * w.z; a0.w += v0 * w.w;
            a1.x += v1 * w.x; a1.y += v1 * w.y; a1.z += v1 * w.z; a1.w += v1 * w.w;
        }
        *reinterpret_cast<float4*>(&sh_part[(c32 * 2 + 0) * 100 + 4 * g25]) = a0;
        *reinterpret_cast<float4*>(&sh_part[(c32 * 2 + 1) * 100 + 4 * g25]) = a1;
    }
    __syncthreads();
    if (tid < 200) {
        float s = bt1[rj];
#pragma unroll
        for (int cc = 0; cc < 32; cc++) s += sh_part[(cc * 2 + rrow) * 100 + rj];
        sh_t1[rrow][rj] = tanhf(s);
    }
    __syncthreads();
    if (tid < 200) {
        float s = bt2[rj];
#pragma unroll 4
        for (int jj = 0; jj < 100; jj++) s += sh_t1[rrow][jj] * Wt2[jj * 100 + rj];
        sh_t2[rrow][rj] = tanhf(s);
    }
    __syncthreads();
    {
        float b = bt3[tid];
        float a0 = b, a1 = b;
        const float* wp = Wt3 + tid;
#pragma unroll 10
        for (int j = 0; j < 100; j++) {
            float w = *wp; wp += 2 * NH;
            a0 += sh_t2[0][j] * w;
            a1 += sh_t2[1][j] * w;
        }
        if (gcol == 0) {
            out[(size_t)(b0 + 0) * NH + col] = a0;
            out[(size_t)(b0 + 1) * NH + col] = a1;
        } else {
            out[(size_t)NB * NH + (size_t)(b0 + 0) * NH + col] = fabsf(a0);
            out[(size_t)NB * NH + (size_t)(b0 + 1) * NH + col] = fabsf(a1);
        }
    }
}

// ---------------------------------------------------------------------------
extern "C" void kernel_launch(void* const* d_in, const int* in_sizes, int n_in,
                              void* d_out, int out_size) {
    const float* x   = (const float*)d_in[0];
    const float* xt  = (const float*)d_in[1];
    const float* Wu1 = (const float*)d_in[2];
    const float* bu1 = (const float*)d_in[3];
    const float* Wu2 = (const float*)d_in[4];
    const float* bu2 = (const float*)d_in[5];
    const float* Wr1 = (const float*)d_in[6];
    const float* br1 = (const float*)d_in[7];
    const float* Wr2 = (const float*)d_in[8];
    const float* br2 = (const float*)d_in[9];
    const float* Wn1 = (const float*)d_in[10];
    const float* bn1 = (const float*)d_in[11];
    const float* Wn2 = (const float*)d_in[12];
    const float* bn2 = (const float*)d_in[13];
    const float* Wo1 = (const float*)d_in[14];
    const float* bo1 = (const float*)d_in[15];
    const float* Wo2 = (const float*)d_in[16];
    const float* bo2 = (const float*)d_in[17];
    const float* Wt1 = (const float*)d_in[18];
    const float* bt1 = (const float*)d_in[19];
    const float* Wt2 = (const float*)d_in[20];
    const float* bt2 = (const float*)d_in[21];
    const float* Wt3 = (const float*)d_in[22];
    const float* bt3 = (const float*)d_in[23];
    float* out = (float*)d_out;

    __half *hWo1, *hWu1, *hWr1, *hWn1, *hWo2, *hWu2, *hWr2, *hWn2;
    cudaGetSymbolAddress((void**)&hWo1, g_hWo1);
    cudaGetSymbolAddress((void**)&hWu1, g_hWu1);
    cudaGetSymbolAddress((void**)&hWr1, g_hWr1);
    cudaGetSymbolAddress((void**)&hWn1, g_hWn1);
    cudaGetSymbolAddress((void**)&hWo2, g_hWo2);
    cudaGetSymbolAddress((void**)&hWu2, g_hWu2);
    cudaGetSymbolAddress((void**)&hWr2, g_hWr2);
    cudaGetSymbolAddress((void**)&hWn2, g_hWn2);

    pack_p1_kernel<<<200, 256>>>(Wo1, hWo1, 512);
    pack_p1_kernel<<<400, 256>>>(Wu1, hWu1, 1024);
    pack_p1_kernel<<<400, 256>>>(Wr1, hWr1, 1024);
    pack_p1_kernel<<<400, 256>>>(Wn1, hWn1, 1024);
    pack_p2_kernel<<<200, 256>>>(Wo2, hWo2, 512);
    pack_p2_kernel<<<200, 256>>>(Wu2, hWu2, 512);
    pack_p2_kernel<<<200, 256>>>(Wr2, hWr2, 512);
    pack_p2_kernel<<<400, 256>>>(Wn2, hWn2, 1024);

    dim3 pgrid(NT, 16);
    prep_xproj_kernel<<<pgrid, 256>>>(x, Wu1, bu1, Wr1, br1, Wn1, bn1);
    odegru_kernel<<<NB / 2, NTH>>>(xt,
        Wt1, bt1, Wt2, bt2, Wt3, bt3,
        bo1, bo2, bu2, br2, bn2, out);
}